// round 15
// baseline (speedup 1.0000x reference)
#include <cuda_runtime.h>
#include <cuda_bf16.h>
#include <cstdint>
#include <math.h>

#define Bb 2
#define Tt 2048
#define Dd 2048
#define Hh 16
#define HDd 128
#define FFd 8192
#define ROWS (Bb*Tt)   /* 4096 */

// tcgen05 only exists in arch-specific (sm_10xa) compilation phases.
#if defined(__CUDA_ARCH_FEAT_SM103_ALL) || defined(__CUDA_ARCH_FEAT_SM100_ALL) || \
    defined(__CUDA_ARCH_FEAT_SM101_ALL) || \
    (defined(__CUDA_ARCH_SPECIFIC__) && (__CUDA_ARCH_SPECIFIC__ >= 1000)) || \
    (defined(__CUDA_ARCH_FAMILY_SPECIFIC__) && (__CUDA_ARCH_FAMILY_SPECIFIC__ >= 1000))
#define HAS_TCGEN05 1
#else
#define HAS_TCGEN05 0
#endif

// ---------------- scratch (no allocations allowed -> device globals) ----------------
__device__ float g_v   [ROWS*Dd];
__device__ float g_ff1 [ROWS*FFd];
// bf16 split buffers (GEMM A-side)
__device__ __nv_bfloat16 g_Ahi[ROWS*FFd];
__device__ __nv_bfloat16 g_Alo[ROWS*FFd];
// weight buffers: 3 pairs for split/GEMM overlap
__device__ __nv_bfloat16 g_Bhi [FFd*Dd];
__device__ __nv_bfloat16 g_Blo [FFd*Dd];
__device__ __nv_bfloat16 g_B2hi[FFd*Dd];
__device__ __nv_bfloat16 g_B2lo[FFd*Dd];
__device__ __nv_bfloat16 g_B3hi[FFd*Dd];
__device__ __nv_bfloat16 g_B3lo[FFd*Dd];
// silu-fused up-GEMM output (down-GEMM's A operand)
__device__ __nv_bfloat16 g_Shi[ROWS*FFd];
__device__ __nv_bfloat16 g_Slo[ROWS*FFd];
// flash inputs: Q/K in [b,t,h*hd]; Vt in [b,h,hd,t]
__device__ __nv_bfloat16 g_fQh[ROWS*Dd];
__device__ __nv_bfloat16 g_fQl[ROWS*Dd];
__device__ __nv_bfloat16 g_fKh[ROWS*Dd];
__device__ __nv_bfloat16 g_fKl[ROWS*Dd];
__device__ __nv_bfloat16 g_fVh[ROWS*Dd];
__device__ __nv_bfloat16 g_fVl[ROWS*Dd];

// ================= helpers =================
__device__ __forceinline__ uint32_t smem_u32(const void* p) {
    uint32_t a;
    asm("{ .reg .u64 t; cvta.to.shared.u64 t, %1; cvt.u32.u64 %0, t; }"
        : "=r"(a) : "l"(p));
    return a;
}

#define SW128(o) ((o) ^ (((o) >> 3) & 0x70))

static constexpr uint64_t DESC_BASE_SW128 =
    (uint64_t(2)  << 61) | (uint64_t(1) << 46) | (uint64_t(64) << 32) | (uint64_t(1) << 16);

#define MMA_IDESC_CG2 0x10400490u   /* M=256, N=256 */
#define MMA_IDESC_QK  0x08100490u   /* M=128, N=64  */
#define MMA_IDESC_PV  0x08200490u   /* M=128, N=128 */

__device__ __forceinline__ void split1(float v, __nv_bfloat16& h, __nv_bfloat16& l) {
    h = __float2bfloat16(v);
    l = __float2bfloat16(v - __bfloat162float(h));
}
__device__ __forceinline__ void split2(float a, float b, uint32_t& hw, uint32_t& lw) {
    __nv_bfloat162 h = __floats2bfloat162_rn(a, b);
    float la = a - __bfloat162float(__low2bfloat16(h));
    float lb = b - __bfloat162float(__high2bfloat16(h));
    __nv_bfloat162 l = __floats2bfloat162_rn(la, lb);
    hw = *reinterpret_cast<uint32_t*>(&h);
    lw = *reinterpret_cast<uint32_t*>(&l);
}

#if HAS_TCGEN05
__device__ __forceinline__ uint64_t mkdesc(uint32_t addr) {
    return DESC_BASE_SW128 | ((uint64_t)(addr >> 4) & 0x3FFF);
}
__device__ __forceinline__ void mma_bf16_ss_cg2(uint32_t d, uint64_t ad, uint64_t bd, uint32_t en) {
    asm volatile(
        "{\n\t.reg .pred p;\n\tsetp.ne.u32 p, %4, 0;\n\t"
        "tcgen05.mma.cta_group::2.kind::f16 [%0], %1, %2, %3, {%5,%5,%5,%5,%5,%5,%5,%5}, p;\n\t}"
        :: "r"(d), "l"(ad), "l"(bd), "r"(MMA_IDESC_CG2), "r"(en), "r"(0u) : "memory");
}
__device__ __forceinline__ void mma_ss_cg1(uint32_t d, uint64_t ad, uint64_t bd,
                                           uint32_t idesc, uint32_t en) {
    asm volatile(
        "{\n\t.reg .pred p;\n\tsetp.ne.u32 p, %4, 0;\n\t"
        "tcgen05.mma.cta_group::1.kind::f16 [%0], %1, %2, %3, {%5,%5,%5,%5}, p;\n\t}"
        :: "r"(d), "l"(ad), "l"(bd), "r"(idesc), "r"(en), "r"(0u) : "memory");
}
__device__ __forceinline__ void mbar_init(uint32_t m, uint32_t cnt) {
    asm volatile("mbarrier.init.shared.b64 [%0], %1;" :: "r"(m), "r"(cnt) : "memory");
}
__device__ __forceinline__ void mbar_wait(uint32_t m, uint32_t parity) {
    asm volatile(
        "{\n\t.reg .pred P1;\n"
        "W%=:\n\t"
        "mbarrier.try_wait.parity.acquire.cta.shared::cta.b64 P1, [%0], %1, 0x989680;\n\t"
        "@P1 bra.uni D%=;\n\t"
        "bra.uni W%=;\n"
        "D%=:\n\t}"
        :: "r"(m), "r"(parity) : "memory");
}
__device__ __forceinline__ void tc_commit_cg1(uint32_t m) {
    asm volatile("tcgen05.commit.cta_group::1.mbarrier::arrive::one.shared::cluster.b64 [%0];"
                 :: "r"(m) : "memory");
}
__device__ __forceinline__ void tc_commit_mc2(uint32_t m) {
    asm volatile(
        "tcgen05.commit.cta_group::2.mbarrier::arrive::one.shared::cluster.multicast::cluster.b64 [%0], %1;"
        :: "r"(m), "h"((uint16_t)0x3) : "memory");
}
__device__ __forceinline__ void mbar_arrive_rank0(uint32_t local_addr) {
    asm volatile(
        "{\n\t.reg .b32 ra;\n\t"
        "mapa.shared::cluster.u32 ra, %0, %1;\n\t"
        "mbarrier.arrive.shared::cluster.b64 _, [ra];\n\t}"
        :: "r"(local_addr), "r"(0) : "memory");
}
__device__ __forceinline__ void ldtm32(uint32_t* r, uint32_t a) {
    asm volatile(
        "tcgen05.ld.sync.aligned.32x32b.x32.b32 "
        "{%0,%1,%2,%3,%4,%5,%6,%7,%8,%9,%10,%11,%12,%13,%14,%15,"
        "%16,%17,%18,%19,%20,%21,%22,%23,%24,%25,%26,%27,%28,%29,%30,%31}, [%32];"
        : "=r"(r[0]),"=r"(r[1]),"=r"(r[2]),"=r"(r[3]),"=r"(r[4]),"=r"(r[5]),"=r"(r[6]),"=r"(r[7]),
          "=r"(r[8]),"=r"(r[9]),"=r"(r[10]),"=r"(r[11]),"=r"(r[12]),"=r"(r[13]),"=r"(r[14]),"=r"(r[15]),
          "=r"(r[16]),"=r"(r[17]),"=r"(r[18]),"=r"(r[19]),"=r"(r[20]),"=r"(r[21]),"=r"(r[22]),"=r"(r[23]),
          "=r"(r[24]),"=r"(r[25]),"=r"(r[26]),"=r"(r[27]),"=r"(r[28]),"=r"(r[29]),"=r"(r[30]),"=r"(r[31])
        : "r"(a));
}
__device__ __forceinline__ void sttm32(uint32_t a, const uint32_t* r) {
    asm volatile(
        "tcgen05.st.sync.aligned.32x32b.x32.b32 [%32], "
        "{%0,%1,%2,%3,%4,%5,%6,%7,%8,%9,%10,%11,%12,%13,%14,%15,"
        "%16,%17,%18,%19,%20,%21,%22,%23,%24,%25,%26,%27,%28,%29,%30,%31};"
        :: "r"(r[0]),"r"(r[1]),"r"(r[2]),"r"(r[3]),"r"(r[4]),"r"(r[5]),"r"(r[6]),"r"(r[7]),
           "r"(r[8]),"r"(r[9]),"r"(r[10]),"r"(r[11]),"r"(r[12]),"r"(r[13]),"r"(r[14]),"r"(r[15]),
           "r"(r[16]),"r"(r[17]),"r"(r[18]),"r"(r[19]),"r"(r[20]),"r"(r[21]),"r"(r[22]),"r"(r[23]),
           "r"(r[24]),"r"(r[25]),"r"(r[26]),"r"(r[27]),"r"(r[28]),"r"(r[29]),"r"(r[30]),"r"(r[31]),
           "r"(a)
        : "memory");
}
__device__ __forceinline__ void cpasync16(uint32_t dst, const void* src) {
    asm volatile("cp.async.cg.shared.global [%0], [%1], 16;" :: "r"(dst), "l"(src) : "memory");
}
__device__ __forceinline__ void cp_arrive(uint32_t m) {
    asm volatile("cp.async.mbarrier.arrive.noinc.shared.b64 [%0];" :: "r"(m) : "memory");
}
#define CP_COMMIT() asm volatile("cp.async.commit_group;" ::: "memory")
#define CP_WAIT0()  asm volatile("cp.async.wait_group 0;" ::: "memory")
#define TC_WAIT_LD() asm volatile("tcgen05.wait::ld.sync.aligned;" ::: "memory")
#define TC_WAIT_ST() asm volatile("tcgen05.wait::st.sync.aligned;" ::: "memory")
#define TC_FENCE_BEFORE() asm volatile("tcgen05.fence::before_thread_sync;" ::: "memory")
#define TC_FENCE_AFTER()  asm volatile("tcgen05.fence::after_thread_sync;" ::: "memory")
#define CLUSTER_SYNC() do { \
    asm volatile("barrier.cluster.arrive.aligned;" ::: "memory"); \
    asm volatile("barrier.cluster.wait.aligned;" ::: "memory"); \
} while (0)
#endif  // HAS_TCGEN05

// ---------------- split fp32 -> bf16 hi/lo (8 elems/thread, 16B ld/st) ----------------
__global__ void __launch_bounds__(256) split_kernel(const float* __restrict__ src,
                                                    __nv_bfloat16* __restrict__ hi,
                                                    __nv_bfloat16* __restrict__ lo,
                                                    int n8)
{
    int idx = blockIdx.x * blockDim.x + threadIdx.x;
    if (idx >= n8) return;
    float4 a = ((const float4*)src)[2 * idx];
    float4 b = ((const float4*)src)[2 * idx + 1];
    uint4 H, L;
    split2(a.x, a.y, H.x, L.x);
    split2(a.z, a.w, H.y, L.y);
    split2(b.x, b.y, H.z, L.z);
    split2(b.z, b.w, H.w, L.w);
    ((uint4*)hi)[idx] = H;
    ((uint4*)lo)[idx] = L;
}

// ---------------- LayerNorm emitting bf16 hi/lo directly ----------------
__global__ void __launch_bounds__(256) ln_split_kernel(const float* __restrict__ x,
                                                       const float* __restrict__ g,
                                                       const float* __restrict__ b,
                                                       __nv_bfloat16* __restrict__ hi,
                                                       __nv_bfloat16* __restrict__ lo)
{
    const int row = blockIdx.x;
    const int tid = threadIdx.x;
    const float* xr = x + (size_t)row * Dd;
    __shared__ float red[256];

    float s = 0.f;
    for (int i = tid; i < Dd; i += 256) s += xr[i];
    red[tid] = s; __syncthreads();
    for (int off = 128; off > 0; off >>= 1) {
        if (tid < off) red[tid] += red[tid + off];
        __syncthreads();
    }
    const float mean = red[0] * (1.f / Dd);
    __syncthreads();

    float v = 0.f;
    for (int i = tid; i < Dd; i += 256) { float d = xr[i] - mean; v += d * d; }
    red[tid] = v; __syncthreads();
    for (int off = 128; off > 0; off >>= 1) {
        if (tid < off) red[tid] += red[tid + off];
        __syncthreads();
    }
    const float rstd = rsqrtf(red[0] * (1.f / Dd) + 1e-5f);

    const int i = tid * 8;
    float4 xa = *(const float4*)(xr + i);
    float4 xb = *(const float4*)(xr + i + 4);
    float4 ga = *(const float4*)(g + i);
    float4 gb = *(const float4*)(g + i + 4);
    float4 ba = *(const float4*)(b + i);
    float4 bb = *(const float4*)(b + i + 4);
    float v0 = (xa.x - mean) * rstd * ga.x + ba.x;
    float v1 = (xa.y - mean) * rstd * ga.y + ba.y;
    float v2 = (xa.z - mean) * rstd * ga.z + ba.z;
    float v3 = (xa.w - mean) * rstd * ga.w + ba.w;
    float v4 = (xb.x - mean) * rstd * gb.x + bb.x;
    float v5 = (xb.y - mean) * rstd * gb.y + bb.y;
    float v6 = (xb.z - mean) * rstd * gb.z + bb.z;
    float v7 = (xb.w - mean) * rstd * gb.w + bb.w;
    uint4 H, L;
    split2(v0, v1, H.x, L.x);
    split2(v2, v3, H.y, L.y);
    split2(v4, v5, H.z, L.z);
    split2(v6, v7, H.w, L.w);
    ((uint4*)(hi + (size_t)row * Dd))[tid] = H;
    ((uint4*)(lo + (size_t)row * Dd))[tid] = L;
}

// ---------------- V transpose+split ----------------
__global__ void __launch_bounds__(256) vtrans_kernel(const float* __restrict__ v,
                                                     __nv_bfloat16* __restrict__ Vth,
                                                     __nv_bfloat16* __restrict__ Vtl)
{
    __shared__ float tile[32][65];
    const int bh = blockIdx.z;
    const int b  = bh >> 4, h = bh & 15;
    const int t0 = blockIdx.x * 64;
    const int d0 = blockIdx.y * 32;
    const int x = threadIdx.x, y = threadIdx.y;  // (32,8)
#pragma unroll
    for (int i = 0; i < 8; i++) {
        const int tt = y + i * 8;
        tile[x][tt] = v[(size_t)(b * Tt + t0 + tt) * Dd + h * HDd + d0 + x];
    }
    __syncthreads();
#pragma unroll
    for (int i = 0; i < 4; i++) {
        const int hdl = y + i * 8;
        const float v0 = tile[hdl][x * 2];
        const float v1 = tile[hdl][x * 2 + 1];
        uint32_t hw, lw;
        split2(v0, v1, hw, lw);
        const size_t idx = (size_t)(bh * HDd + d0 + hdl) * Tt + t0 + x * 2;
        *(uint32_t*)(Vth + idx) = hw;
        *(uint32_t*)(Vtl + idx) = lw;
    }
}

// ============ cg2 GEMM, warp-specialized; epilogue modes: plain / rope+split / silu+split ============
#define NSTAGE 3
#define STAGE_BYTES 65536
#define GEMM_SMEM (1024 + NSTAGE * STAGE_BYTES)
#define GEMM_THREADS 288

__global__ void __launch_bounds__(GEMM_THREADS, 1) __cluster_dims__(2, 1, 1)
mma_gemm_kernel(const __nv_bfloat16* __restrict__ Ah, const __nv_bfloat16* __restrict__ Al,
                const __nv_bfloat16* __restrict__ Bh, const __nv_bfloat16* __restrict__ Bl,
                const float* __restrict__ bias, const float* __restrict__ resid,
                float* __restrict__ C,
                const float* __restrict__ rope,
                const float* __restrict__ gate,
                __nv_bfloat16* __restrict__ Chi, __nv_bfloat16* __restrict__ Clo,
                int M, int N, int K)
{
    extern __shared__ char smem[];
#if HAS_TCGEN05
    const uint32_t sbase = smem_u32(smem);
    const int tid  = threadIdx.x;
    const int wid  = tid >> 5;
    const int lane = tid & 31;
    const int rank = blockIdx.x & 1;
    const int bn   = (blockIdx.x >> 1) * 256;
    const int bm   = blockIdx.y * 256;

    const uint32_t tile_abs = (sbase + 128 + 1023) & ~1023u;
    const uint32_t mb_full  = sbase + 8;
    const uint32_t mb_f2    = sbase + 32;
    const uint32_t mb_empty = sbase + 56;

    if (wid == 0) {
        asm volatile("tcgen05.alloc.cta_group::2.sync.aligned.shared::cta.b32 [%0], %1;"
                     :: "r"(sbase), "r"(256u) : "memory");
        asm volatile("tcgen05.relinquish_alloc_permit.cta_group::2.sync.aligned;");
    }
    if (tid == 0) {
#pragma unroll
        for (int s = 0; s < NSTAGE; s++) {
            mbar_init(mb_full  + s * 8, 256);
            mbar_init(mb_f2    + s * 8, 2);
            mbar_init(mb_empty + s * 8, 1);
        }
    }
    __syncthreads();
    CLUSTER_SYNC();

    uint32_t tmem;
    asm volatile("ld.shared.b32 %0, [%1];" : "=r"(tmem) : "r"(sbase));

    const int n = K >> 6;

    if (tid < 256) {
        const int r  = tid >> 1;
        const int hh = tid & 1;
        const uint32_t off = r * 128 + hh * 64;
        const __nv_bfloat16* AgH = Ah + (size_t)(bm + rank * 128 + r) * K + hh * 32;
        const __nv_bfloat16* AgL = Al + (size_t)(bm + rank * 128 + r) * K + hh * 32;
        const __nv_bfloat16* BgH = Bh + (size_t)(bn + rank * 128 + r) * K + hh * 32;
        const __nv_bfloat16* BgL = Bl + (size_t)(bn + rank * 128 + r) * K + hh * 32;

        for (int c = 0; c < n; c++) {
            const int s = c % NSTAGE;
            const int use = c / NSTAGE;
            if (c >= NSTAGE) mbar_wait(mb_empty + s * 8, (use - 1) & 1);

            const uint32_t sb = tile_abs + s * STAGE_BYTES;
            const size_t kof = (size_t)c * 64;
#pragma unroll
            for (int j = 0; j < 4; j++) {
                const uint32_t o = SW128(off + j * 16);
                cpasync16(sb + o,         AgH + kof + j * 8);
                cpasync16(sb + 16384 + o, AgL + kof + j * 8);
                cpasync16(sb + 32768 + o, BgH + kof + j * 8);
                cpasync16(sb + 49152 + o, BgL + kof + j * 8);
            }
            cp_arrive(mb_full + s * 8);
        }
    } else if (tid == 256) {
        for (int i = 0; i < n; i++) {
            const int si = i % NSTAGE;
            mbar_wait(mb_full + si * 8, (i / NSTAGE) & 1);
            mbar_arrive_rank0(mb_f2 + si * 8);
            if (rank == 0) {
                mbar_wait(mb_f2 + si * 8, (i / NSTAGE) & 1);
                asm volatile("fence.proxy.async.shared::cta;" ::: "memory");
                const uint32_t sbi = tile_abs + si * STAGE_BYTES;
                const uint64_t ah = mkdesc(sbi);
                const uint64_t al = mkdesc(sbi + 16384);
                const uint64_t bh = mkdesc(sbi + 32768);
                const uint64_t bl = mkdesc(sbi + 49152);
#pragma unroll
                for (int k = 0; k < 4; k++)
                    mma_bf16_ss_cg2(tmem, ah + k * 2, bh + k * 2, (i > 0 || k > 0) ? 1u : 0u);
#pragma unroll
                for (int k = 0; k < 4; k++)
                    mma_bf16_ss_cg2(tmem, ah + k * 2, bl + k * 2, 1u);
#pragma unroll
                for (int k = 0; k < 4; k++)
                    mma_bf16_ss_cg2(tmem, al + k * 2, bh + k * 2, 1u);
                tc_commit_mc2(mb_empty + si * 8);
            }
        }
    }

    {
        const int i = n - 1, si = i % NSTAGE;
        mbar_wait(mb_empty + si * 8, (i / NSTAGE) & 1);
    }
    TC_FENCE_AFTER();

    if (wid < 8) {
        const int sub  = wid & 3;
        const int half = wid >> 2;
        const int row  = bm + rank * 128 + sub * 32 + lane;
        const float* rrow = resid ? resid + (size_t)row * N : nullptr;
        const float* grow = gate ? gate + (size_t)row * N : nullptr;
        float* crow = C ? C + (size_t)row * N : nullptr;
#pragma unroll 1
        for (int half2 = 0; half2 < 2; half2++) {
#pragma unroll 1
            for (int c32 = 0; c32 < 2; c32++) {
                uint32_t d[32];
                ldtm32(d, tmem + half2 * 128 + half * 64 + c32 * 32);
                TC_WAIT_LD();
                const int col0 = bn + half2 * 128 + half * 64 + c32 * 32;
                if (rope) {
                    uint2* hrow = (uint2*)(Chi + (size_t)row * N + col0);
                    uint2* lrow = (uint2*)(Clo + (size_t)row * N + col0);
#pragma unroll
                    for (int t2 = 0; t2 < 8; t2++) {
                        const int c = col0 + t2 * 4;
                        const float a0 = __uint_as_float(d[t2 * 4 + 0]) + bias[c + 0];
                        const float b0 = __uint_as_float(d[t2 * 4 + 1]) + bias[c + 1];
                        const float a1 = __uint_as_float(d[t2 * 4 + 2]) + bias[c + 2];
                        const float b1 = __uint_as_float(d[t2 * 4 + 3]) + bias[c + 3];
                        const float cr0 = rope[c + 0], ci0 = rope[c + 1];
                        const float cr1 = rope[c + 2], ci1 = rope[c + 3];
                        uint2 hv, lv;
                        split2(a0 * cr0 - b0 * ci0, a0 * ci0 + b0 * cr0, hv.x, lv.x);
                        split2(a1 * cr1 - b1 * ci1, a1 * ci1 + b1 * cr1, hv.y, lv.y);
                        hrow[t2] = hv;
                        lrow[t2] = lv;
                    }
                } else if (grow) {
                    uint2* hrow = (uint2*)(Chi + (size_t)row * N + col0);
                    uint2* lrow = (uint2*)(Clo + (size_t)row * N + col0);
#pragma unroll
                    for (int t2 = 0; t2 < 8; t2++) {
                        const int c = col0 + t2 * 4;
                        float4 gv = *(const float4*)(grow + c);
                        const float u0 = __uint_as_float(d[t2 * 4 + 0]) + bias[c + 0];
                        const float u1 = __uint_as_float(d[t2 * 4 + 1]) + bias[c + 1];
                        const float u2 = __uint_as_float(d[t2 * 4 + 2]) + bias[c + 2];
                        const float u3 = __uint_as_float(d[t2 * 4 + 3]) + bias[c + 3];
                        const float v0 = gv.x / (1.f + __expf(-gv.x)) * u0;
                        const float v1 = gv.y / (1.f + __expf(-gv.y)) * u1;
                        const float v2 = gv.z / (1.f + __expf(-gv.z)) * u2;
                        const float v3 = gv.w / (1.f + __expf(-gv.w)) * u3;
                        uint2 hv, lv;
                        split2(v0, v1, hv.x, lv.x);
                        split2(v2, v3, hv.y, lv.y);
                        hrow[t2] = hv;
                        lrow[t2] = lv;
                    }
                } else if (rrow) {
#pragma unroll
                    for (int j = 0; j < 32; j++)
                        crow[col0 + j] = __uint_as_float(d[j]) + bias[col0 + j] + rrow[col0 + j];
                } else {
#pragma unroll
                    for (int j = 0; j < 32; j++)
                        crow[col0 + j] = __uint_as_float(d[j]) + bias[col0 + j];
                }
            }
        }
    }
    __syncthreads();
    if (wid == 0) {
        asm volatile("tcgen05.dealloc.cta_group::2.sync.aligned.b32 %0, %1;"
                     :: "r"(tmem), "r"(256u));
    }
    CLUSTER_SYNC();
#else
    float* As = (float*)smem;
    float* Bs = As + 8 * 128;
    const int tid = threadIdx.x;
    const int rank = blockIdx.x & 1;
    const int bm = blockIdx.y * 256 + rank * 128;
    const int bn0 = (blockIdx.x >> 1) * 256;
    const int lr  = tid >> 1;
    const int lcc = (tid & 1) * 4;
    const int tx = tid & 15, ty = tid >> 4;

    for (int h = 0; h < 2; h++) {
        const int bn = bn0 + h * 128;
        float acc[8][8];
#pragma unroll
        for (int i = 0; i < 8; i++)
#pragma unroll
            for (int j = 0; j < 8; j++) acc[i][j] = 0.f;

        for (int k0 = 0; k0 < K; k0 += 8) {
            if (tid < 256) {
                const __nv_bfloat16* aph = Ah + (size_t)(bm + lr) * K + k0 + lcc;
                const __nv_bfloat16* apl = Al + (size_t)(bm + lr) * K + k0 + lcc;
                const __nv_bfloat16* bph = Bh + (size_t)(bn + lr) * K + k0 + lcc;
                const __nv_bfloat16* bpl = Bl + (size_t)(bn + lr) * K + k0 + lcc;
#pragma unroll
                for (int j = 0; j < 4; j++) {
                    As[(lcc + j) * 128 + lr] = __bfloat162float(aph[j]) + __bfloat162float(apl[j]);
                    Bs[(lcc + j) * 128 + lr] = __bfloat162float(bph[j]) + __bfloat162float(bpl[j]);
                }
            }
            __syncthreads();
            if (tid < 256) {
#pragma unroll
                for (int kk = 0; kk < 8; kk++) {
                    float a[8], bb[8];
#pragma unroll
                    for (int i = 0; i < 8; i++)
                        a[i] = As[kk * 128 + ((i & 4) << 4) + ty * 4 + (i & 3)];
#pragma unroll
                    for (int j = 0; j < 8; j++)
                        bb[j] = Bs[kk * 128 + ((j & 4) << 4) + tx * 4 + (j & 3)];
#pragma unroll
                    for (int i = 0; i < 8; i++)
#pragma unroll
                        for (int j = 0; j < 8; j++)
                            acc[i][j] += a[i] * bb[j];
                }
            }
            __syncthreads();
        }

        if (tid < 256) {
#pragma unroll
            for (int i = 0; i < 8; i++) {
                const int row = bm + ((i & 4) << 4) + ty * 4 + (i & 3);
                if (rope) {
#pragma unroll
                    for (int j = 0; j < 8; j += 2) {
                        const int c = bn + ((j & 4) << 4) + tx * 4 + (j & 3);
                        float a0 = acc[i][j] + bias[c];
                        float b0 = acc[i][j + 1] + bias[c + 1];
                        float r0 = a0 * rope[c] - b0 * rope[c + 1];
                        float r1 = a0 * rope[c + 1] + b0 * rope[c];
                        __nv_bfloat16 hh, ll;
                        split1(r0, hh, ll);
                        Chi[(size_t)row * N + c] = hh; Clo[(size_t)row * N + c] = ll;
                        split1(r1, hh, ll);
                        Chi[(size_t)row * N + c + 1] = hh; Clo[(size_t)row * N + c + 1] = ll;
                    }
                } else if (gate) {
#pragma unroll
                    for (int j = 0; j < 8; j++) {
                        const int c = bn + ((j & 4) << 4) + tx * 4 + (j & 3);
                        float gvv = gate[(size_t)row * N + c];
                        float u = acc[i][j] + bias[c];
                        float vv = gvv / (1.f + __expf(-gvv)) * u;
                        __nv_bfloat16 hh, ll;
                        split1(vv, hh, ll);
                        Chi[(size_t)row * N + c] = hh; Clo[(size_t)row * N + c] = ll;
                    }
                } else {
#pragma unroll
                    for (int j = 0; j < 8; j++) {
                        const int col = bn + ((j & 4) << 4) + tx * 4 + (j & 3);
                        float vv = acc[i][j] + bias[col];
                        if (resid) vv += resid[(size_t)row * N + col];
                        C[(size_t)row * N + col] = vv;
                    }
                }
            }
        }
    }
#endif
}

// ============ tcgen05 flash attention (unchanged from R14, passing) ============
#define FLASH_SMEM (1024 + 160 * 1024 + 1024)

__global__ void __launch_bounds__(256, 1) flash_mma_kernel(
    const __nv_bfloat16* __restrict__ Qh, const __nv_bfloat16* __restrict__ Ql,
    const __nv_bfloat16* __restrict__ Kh, const __nv_bfloat16* __restrict__ Kl,
    const __nv_bfloat16* __restrict__ Vh, const __nv_bfloat16* __restrict__ Vl,
    __nv_bfloat16* __restrict__ Ohi, __nv_bfloat16* __restrict__ Olo)
{
    extern __shared__ char smem[];
#if HAS_TCGEN05
    const uint32_t sbase = smem_u32(smem);
    const int tid  = threadIdx.x;
    const int wid  = tid >> 5;
    const int lane = tid & 31;
    const int qb = gridDim.x - 1 - blockIdx.x;
    const int h = blockIdx.y, b = blockIdx.z;
    const int q0 = qb * 128;

    const uint32_t mb_qk = sbase + 8;
    const uint32_t mb_pv = sbase + 16;
    int*   flags  = (int*)(smem + 24);
    float* redbuf = (float*)(smem + 64);
    const uint32_t tile_abs = (sbase + 576 + 1023) & ~1023u;
    const uint32_t tile_off = tile_abs - sbase;

    if (wid == 0) {
        asm volatile("tcgen05.alloc.cta_group::1.sync.aligned.shared::cta.b32 [%0], %1;"
                     :: "r"(sbase), "r"(256u) : "memory");
        asm volatile("tcgen05.relinquish_alloc_permit.cta_group::1.sync.aligned;");
    }
    if (tid == 0) { mbar_init(mb_qk, 1); mbar_init(mb_pv, 1); }
    __syncthreads();
    uint32_t tmem;
    asm volatile("ld.shared.b32 %0, [%1];" : "=r"(tmem) : "r"(sbase));
    const uint32_t tm_S = tmem;
    const uint32_t tm_O = tmem + 64;

#pragma unroll
    for (int i = 0; i < 2; i++) {
        int u = tid * 2 + i;
        int buf = u >> 8, rem = u & 255, half = rem >> 7, row = rem & 127;
        const __nv_bfloat16* src = (buf ? Ql : Qh)
            + (size_t)(b * Tt + q0 + row) * Dd + h * HDd + half * 64;
        uint32_t dst = tile_abs + buf * 32768 + half * 16384;
        uint32_t off = row * 128;
#pragma unroll
        for (int j = 0; j < 8; j++)
            cpasync16(dst + SW128(off + j * 16), src + j * 8);
    }
    CP_COMMIT();

    const int sw   = wid & 3;
    const int colh = wid >> 2;
    const int row  = sw * 32 + lane;
    const float scale = 0.088388347648318447f;

    float m = -1e30f, l = 0.f;
    const int nt = 2 * qb + 2;

    for (int t = 0; t < nt; t++) {
        const int j0 = t * 64;
        if (t > 0) mbar_wait(mb_pv, (t - 1) & 1);

#pragma unroll
        for (int i = 0; i < 2; i++) {
            int u = tid * 2 + i;
            const __nv_bfloat16* src;
            uint32_t dst, off;
            if (u < 256) {
                int kr = u & 63, half = (u >> 6) & 1, buf = u >> 7;
                src = (buf ? Kl : Kh) + (size_t)(b * Tt + j0 + kr) * Dd + h * HDd + half * 64;
                dst = tile_abs + 65536 + buf * 16384 + half * 8192;
                off = kr * 128;
            } else {
                int u2 = u - 256;
                int vr = u2 & 127, buf = u2 >> 7;
                src = (buf ? Vl : Vh) + (size_t)((b * Hh + h) * HDd + vr) * Tt + j0;
                dst = tile_abs + 98304 + buf * 16384;
                off = vr * 128;
            }
#pragma unroll
            for (int j = 0; j < 8; j++)
                cpasync16(dst + SW128(off + j * 16), src + j * 8);
        }
        CP_COMMIT();
        CP_WAIT0();
        __syncthreads();

        if (tid == 0) {
            asm volatile("fence.proxy.async.shared::cta;" ::: "memory");
            uint64_t qd[2][2], kd[2][2];
            qd[0][0] = mkdesc(tile_abs);          qd[0][1] = mkdesc(tile_abs + 16384);
            qd[1][0] = mkdesc(tile_abs + 32768);  qd[1][1] = mkdesc(tile_abs + 49152);
            kd[0][0] = mkdesc(tile_abs + 65536);  kd[0][1] = mkdesc(tile_abs + 73728);
            kd[1][0] = mkdesc(tile_abs + 81920);  kd[1][1] = mkdesc(tile_abs + 90112);
            int first = 1;
#pragma unroll
            for (int c3 = 0; c3 < 3; c3++) {
                const int ab = (c3 == 2) ? 1 : 0;
                const int bb = (c3 == 1) ? 1 : 0;
#pragma unroll
                for (int ks = 0; ks < 8; ks++) {
                    const int half = ks >> 2;
                    const uint64_t o = (uint64_t)((ks & 3) * 2);
                    mma_ss_cg1(tm_S, qd[ab][half] + o, kd[bb][half] + o,
                               MMA_IDESC_QK, first ? 0u : 1u);
                    first = 0;
                }
            }
            tc_commit_cg1(mb_qk);
        }
        mbar_wait(mb_qk, t & 1);
        TC_FENCE_AFTER();

        if (wid < 4) {
            uint32_t sr[64];
            ldtm32(sr,      tm_S);
            ldtm32(sr + 32, tm_S + 32);
            TC_WAIT_LD();
            float sv[64];
            float tmax = -1e30f;
#pragma unroll
            for (int c = 0; c < 64; c++) {
                float x = __uint_as_float(sr[c]) * scale;
                if (j0 + c > q0 + row) x = -1e30f;
                sv[c] = x;
                tmax = fmaxf(tmax, x);
            }
            const float mnew = fmaxf(m, tmax);
            const float alpha = __expf(m - mnew);
            m = mnew;
            float psum = 0.f;
#pragma unroll
            for (int c = 0; c < 64; c++) {
                float p = __expf(sv[c] - mnew);
                sv[c] = p;
                psum += p;
            }
            l = l * alpha + psum;
            const uint32_t prow = row * 128;
#pragma unroll
            for (int g = 0; g < 16; g++) {
                const int c = g * 4;
                uint2 hv, lv;
                split2(sv[c],     sv[c + 1], hv.x, lv.x);
                split2(sv[c + 2], sv[c + 3], hv.y, lv.y);
                const uint32_t o = SW128(prow + c * 2);
                *(uint2*)(smem + tile_off + 131072 + o) = hv;
                *(uint2*)(smem + tile_off + 147456 + o) = lv;
            }
            asm volatile("fence.proxy.async.shared::cta;" ::: "memory");
            redbuf[row] = alpha;
            unsigned bal = __ballot_sync(0xffffffffu, alpha < 0.999999f);
            if (lane == 0) flags[wid] = (bal != 0) ? 1 : 0;
        }
        __syncthreads();

        if (t > 0 && ((volatile int*)flags)[sw]) {
            const float av = ((volatile float*)redbuf)[row];
            uint32_t o0[32], o1[32];
            ldtm32(o0, tm_O + colh * 64);
            ldtm32(o1, tm_O + colh * 64 + 32);
            TC_WAIT_LD();
#pragma unroll
            for (int j = 0; j < 32; j++) {
                o0[j] = __float_as_uint(__uint_as_float(o0[j]) * av);
                o1[j] = __float_as_uint(__uint_as_float(o1[j]) * av);
            }
            sttm32(tm_O + colh * 64,      o0);
            sttm32(tm_O + colh * 64 + 32, o1);
            TC_WAIT_ST();
        }
        TC_FENCE_BEFORE();
        __syncthreads();

        if (tid == 0) {
            TC_FENCE_AFTER();
            asm volatile("fence.proxy.async.shared::cta;" ::: "memory");
            uint64_t pd[2], vd[2];
            pd[0] = mkdesc(tile_abs + 131072); pd[1] = mkdesc(tile_abs + 147456);
            vd[0] = mkdesc(tile_abs + 98304);  vd[1] = mkdesc(tile_abs + 114688);
            int first = (t == 0) ? 1 : 0;
#pragma unroll
            for (int c3 = 0; c3 < 3; c3++) {
                const int ab = (c3 == 1) ? 1 : 0;
                const int bb = (c3 == 2) ? 1 : 0;
#pragma unroll
                for (int ks = 0; ks < 4; ks++) {
                    const uint64_t o = (uint64_t)(ks * 2);
                    mma_ss_cg1(tm_O, pd[ab] + o, vd[bb] + o,
                               MMA_IDESC_PV, first ? 0u : 1u);
                    first = 0;
                }
            }
            tc_commit_cg1(mb_pv);
        }
    }

    mbar_wait(mb_pv, (nt - 1) & 1);
    TC_FENCE_AFTER();
    if (wid < 4) redbuf[row] = 1.f / l;
    __syncthreads();

    {
        const float linv = ((volatile float*)redbuf)[row];
        uint32_t o0[32], o1[32];
        ldtm32(o0, tm_O + colh * 64);
        ldtm32(o1, tm_O + colh * 64 + 32);
        TC_WAIT_LD();
        const size_t obase = (size_t)(b * Tt + q0 + row) * Dd + h * HDd + colh * 64;
        uint32_t* hrow = (uint32_t*)(Ohi + obase);
        uint32_t* lrow = (uint32_t*)(Olo + obase);
#pragma unroll
        for (int j = 0; j < 16; j++) {
            uint32_t hw, lw;
            split2(__uint_as_float(o0[2 * j]) * linv,
                   __uint_as_float(o0[2 * j + 1]) * linv, hw, lw);
            hrow[j] = hw; lrow[j] = lw;
        }
#pragma unroll
        for (int j = 0; j < 16; j++) {
            uint32_t hw, lw;
            split2(__uint_as_float(o1[2 * j]) * linv,
                   __uint_as_float(o1[2 * j + 1]) * linv, hw, lw);
            hrow[16 + j] = hw; lrow[16 + j] = lw;
        }
    }
    __syncthreads();
    if (wid == 0) {
        asm volatile("tcgen05.dealloc.cta_group::1.sync.aligned.b32 %0, %1;"
                     :: "r"(tmem), "r"(256u));
    }
#else
    const int tid = threadIdx.x;
    const int qb = gridDim.x - 1 - blockIdx.x;
    const int h = blockIdx.y, b = blockIdx.z;
    const int q0 = qb * 128;
    if (tid < 128) {
        const int rq = q0 + tid;
        float m = -1e30f, l = 0.f, o[128];
        for (int d = 0; d < 128; d++) o[d] = 0.f;
        for (int j = 0; j <= rq; j++) {
            float s = 0.f;
            const size_t qo = (size_t)(b * Tt + rq) * Dd + h * HDd;
            const size_t ko = (size_t)(b * Tt + j) * Dd + h * HDd;
            for (int d = 0; d < 128; d++) {
                float qv = __bfloat162float(Qh[qo + d]) + __bfloat162float(Ql[qo + d]);
                float kv = __bfloat162float(Kh[ko + d]) + __bfloat162float(Kl[ko + d]);
                s += qv * kv;
            }
            s *= 0.088388347648318447f;
            float mn = fmaxf(m, s);
            float al = __expf(m - mn), p = __expf(s - mn);
            m = mn;
            l = l * al + p;
            const size_t vo = (size_t)(b * Hh + h) * HDd;
            for (int d = 0; d < 128; d++) {
                float vv = __bfloat162float(Vh[(vo + d) * Tt + j]) +
                           __bfloat162float(Vl[(vo + d) * Tt + j]);
                o[d] = o[d] * al + p * vv;
            }
        }
        const size_t obase = (size_t)(b * Tt + rq) * Dd + h * HDd;
        for (int d = 0; d < 128; d++) {
            __nv_bfloat16 hi, lo;
            split1(o[d] / l, hi, lo);
            Ohi[obase + d] = hi;
            Olo[obase + d] = lo;
        }
    }
#endif
}

// ---------------- launch ----------------
extern "C" void kernel_launch(void* const* d_in, const int* in_sizes, int n_in,
                              void* d_out, int out_size)
{
    const float* x   = (const float*)d_in[0];
    const float* fr  = (const float*)d_in[1];
    const float* Wq  = (const float*)d_in[2];
    const float* bq  = (const float*)d_in[3];
    const float* Wk  = (const float*)d_in[4];
    const float* bk  = (const float*)d_in[5];
    const float* Wv  = (const float*)d_in[6];
    const float* bv  = (const float*)d_in[7];
    const float* Wo  = (const float*)d_in[8];
    const float* bo  = (const float*)d_in[9];
    const float* g1  = (const float*)d_in[10];
    const float* be1 = (const float*)d_in[11];
    const float* g2  = (const float*)d_in[12];
    const float* be2 = (const float*)d_in[13];
    const float* Wg  = (const float*)d_in[14];
    const float* bg  = (const float*)d_in[15];
    const float* Wu  = (const float*)d_in[16];
    const float* bu  = (const float*)d_in[17];
    const float* Wd  = (const float*)d_in[18];
    const float* bd  = (const float*)d_in[19];
    float* out = (float*)d_out;

    float *v, *ff1;
    __nv_bfloat16 *Ahi, *Alo, *B1h, *B1l, *B2h, *B2l, *B3h, *B3l, *Shi, *Slo;
    __nv_bfloat16 *fQh, *fQl, *fKh, *fKl, *fVh, *fVl;
    cudaGetSymbolAddress((void**)&v,    g_v);
    cudaGetSymbolAddress((void**)&ff1,  g_ff1);
    cudaGetSymbolAddress((void**)&Ahi,  g_Ahi);
    cudaGetSymbolAddress((void**)&Alo,  g_Alo);
    cudaGetSymbolAddress((void**)&B1h,  g_Bhi);
    cudaGetSymbolAddress((void**)&B1l,  g_Blo);
    cudaGetSymbolAddress((void**)&B2h,  g_B2hi);
    cudaGetSymbolAddress((void**)&B2l,  g_B2lo);
    cudaGetSymbolAddress((void**)&B3h,  g_B3hi);
    cudaGetSymbolAddress((void**)&B3l,  g_B3lo);
    cudaGetSymbolAddress((void**)&Shi,  g_Shi);
    cudaGetSymbolAddress((void**)&Slo,  g_Slo);
    cudaGetSymbolAddress((void**)&fQh,  g_fQh);
    cudaGetSymbolAddress((void**)&fQl,  g_fQl);
    cudaGetSymbolAddress((void**)&fKh,  g_fKh);
    cudaGetSymbolAddress((void**)&fKl,  g_fKl);
    cudaGetSymbolAddress((void**)&fVh,  g_fVh);
    cudaGetSymbolAddress((void**)&fVl,  g_fVl);

    cudaFuncSetAttribute(mma_gemm_kernel, cudaFuncAttributeMaxDynamicSharedMemorySize, GEMM_SMEM);
    cudaFuncSetAttribute(flash_mma_kernel, cudaFuncAttributeMaxDynamicSharedMemorySize, FLASH_SMEM);

    // side stream + events for weight-split overlap (created once; capture-safe fork/join)
    static cudaStream_t s1 = nullptr;
    static cudaEvent_t eFork, e1, e2, e3, e4, e5, e6, eQ, eK, eV, eO;
    if (!s1) {
        cudaStreamCreateWithFlags(&s1, cudaStreamNonBlocking);
        cudaEventCreateWithFlags(&eFork, cudaEventDisableTiming);
        cudaEventCreateWithFlags(&e1, cudaEventDisableTiming);
        cudaEventCreateWithFlags(&e2, cudaEventDisableTiming);
        cudaEventCreateWithFlags(&e3, cudaEventDisableTiming);
        cudaEventCreateWithFlags(&e4, cudaEventDisableTiming);
        cudaEventCreateWithFlags(&e5, cudaEventDisableTiming);
        cudaEventCreateWithFlags(&e6, cudaEventDisableTiming);
        cudaEventCreateWithFlags(&eQ, cudaEventDisableTiming);
        cudaEventCreateWithFlags(&eK, cudaEventDisableTiming);
        cudaEventCreateWithFlags(&eV, cudaEventDisableTiming);
        cudaEventCreateWithFlags(&eO, cudaEventDisableTiming);
    }

    const int DW  = Dd * Dd;     // 4M
    const int FW  = FFd * Dd;    // 16M

#define SPLIT_ON(st, src, hi, lo, n) \
    split_kernel<<<((n)/8 + 255)/256, 256, 0, st>>>(src, hi, lo, (n)/8)

    // ---- main stream (0) + side stream s1 choreography ----
    // 1) LN1 -> Ahi/Alo ; split(Wq) -> B1   (critical path)
    ln_split_kernel<<<ROWS, 256>>>(x, g1, be1, Ahi, Alo);
    SPLIT_ON(0, Wq, B1h, B1l, DW);

    // fork: side stream does the other splits, each joined before its consumer GEMM
    cudaEventRecord(eFork, 0);
    cudaStreamWaitEvent(s1, eFork, 0);
    SPLIT_ON(s1, Wk, B2h, B2l, DW);
    cudaEventRecord(e1, s1);

    dim3 gD(2 * (Dd / 256), ROWS / 256);
    dim3 gF(2 * (FFd / 256), ROWS / 256);

    // 2) GEMM_Q (B1, rope -> fQ)
    mma_gemm_kernel<<<gD, GEMM_THREADS, GEMM_SMEM>>>(
        Ahi, Alo, B1h, B1l, bq, nullptr, nullptr, fr, nullptr, fQh, fQl, ROWS, Dd, Dd);
    cudaEventRecord(eQ, 0);

    // s1: after GEMM_Q released B1 -> split(Wv) -> B1
    cudaStreamWaitEvent(s1, eQ, 0);
    SPLIT_ON(s1, Wv, B1h, B1l, DW);
    cudaEventRecord(e2, s1);

    // GEMM_K (B2, rope -> fK)
    cudaStreamWaitEvent(0, e1, 0);
    mma_gemm_kernel<<<gD, GEMM_THREADS, GEMM_SMEM>>>(
        Ahi, Alo, B2h, B2l, bk, nullptr, nullptr, fr, nullptr, fKh, fKl, ROWS, Dd, Dd);
    cudaEventRecord(eK, 0);

    // s1: after GEMM_K released B2 -> split(Wo) -> B2
    cudaStreamWaitEvent(s1, eK, 0);
    SPLIT_ON(s1, Wo, B2h, B2l, DW);
    cudaEventRecord(e3, s1);

    // GEMM_V (B1 -> fp32 v)
    cudaStreamWaitEvent(0, e2, 0);
    mma_gemm_kernel<<<gD, GEMM_THREADS, GEMM_SMEM>>>(
        Ahi, Alo, B1h, B1l, bv, nullptr, v, nullptr, nullptr, nullptr, nullptr, ROWS, Dd, Dd);
    cudaEventRecord(eV, 0);

    // s1: after GEMM_V released B1 -> split(Wg) -> B1 ; split(Wu) -> B3
    cudaStreamWaitEvent(s1, eV, 0);
    SPLIT_ON(s1, Wg, B1h, B1l, FW);
    cudaEventRecord(e4, s1);
    SPLIT_ON(s1, Wu, B3h, B3l, FW);
    cudaEventRecord(e5, s1);

    // 3) V transpose+split ; 4) flash
    vtrans_kernel<<<dim3(Tt / 64, HDd / 32, Bb * Hh), dim3(32, 8)>>>(v, fVh, fVl);
    flash_mma_kernel<<<dim3(Tt / 128, Hh, Bb), 256, FLASH_SMEM>>>(
        fQh, fQl, fKh, fKl, fVh, fVl, Ahi, Alo);

    // 5) GEMM_O (B2) + residual(x) -> out
    cudaStreamWaitEvent(0, e3, 0);
    mma_gemm_kernel<<<gD, GEMM_THREADS, GEMM_SMEM>>>(
        Ahi, Alo, B2h, B2l, bo, x, out, nullptr, nullptr, nullptr, nullptr, ROWS, Dd, Dd);
    cudaEventRecord(eO, 0);

    // s1: after GEMM_O released B2 -> split(Wd) -> B2
    cudaStreamWaitEvent(s1, eO, 0);
    SPLIT_ON(s1, Wd, B2h, B2l, FW);
    cudaEventRecord(e6, s1);

    // 6) LN2 -> Ahi/Alo
    ln_split_kernel<<<ROWS, 256>>>(out, g2, be2, Ahi, Alo);

    // 7) gate (B1 -> fp32 ff1) ; up (B3, fused silu(gate)*u -> Shi/Slo)
    cudaStreamWaitEvent(0, e4, 0);
    mma_gemm_kernel<<<gF, GEMM_THREADS, GEMM_SMEM>>>(
        Ahi, Alo, B1h, B1l, bg, nullptr, ff1, nullptr, nullptr, nullptr, nullptr, ROWS, FFd, Dd);
    cudaStreamWaitEvent(0, e5, 0);
    mma_gemm_kernel<<<gF, GEMM_THREADS, GEMM_SMEM>>>(
        Ahi, Alo, B3h, B3l, bu, nullptr, nullptr, nullptr, ff1, Shi, Slo, ROWS, FFd, Dd);

    // 9) down (B2) + residual(out) -> out
    cudaStreamWaitEvent(0, e6, 0);
    mma_gemm_kernel<<<gD, GEMM_THREADS, GEMM_SMEM>>>(
        Shi, Slo, B2h, B2l, bd, out, out, nullptr, nullptr, nullptr, nullptr, ROWS, Dd, FFd);
}

// round 17
// speedup vs baseline: 1.0117x; 1.0117x over previous
#include <cuda_runtime.h>
#include <cuda_bf16.h>
#include <cstdint>
#include <math.h>

#define Bb 2
#define Tt 2048
#define Dd 2048
#define Hh 16
#define HDd 128
#define FFd 8192
#define ROWS (Bb*Tt)   /* 4096 */

// tcgen05 only exists in arch-specific (sm_10xa) compilation phases.
#if defined(__CUDA_ARCH_FEAT_SM103_ALL) || defined(__CUDA_ARCH_FEAT_SM100_ALL) || \
    defined(__CUDA_ARCH_FEAT_SM101_ALL) || \
    (defined(__CUDA_ARCH_SPECIFIC__) && (__CUDA_ARCH_SPECIFIC__ >= 1000)) || \
    (defined(__CUDA_ARCH_FAMILY_SPECIFIC__) && (__CUDA_ARCH_FAMILY_SPECIFIC__ >= 1000))
#define HAS_TCGEN05 1
#else
#define HAS_TCGEN05 0
#endif

// ---------------- scratch (no allocations allowed -> device globals) ----------------
__device__ float g_v   [ROWS*Dd];
__device__ float g_ff1 [ROWS*FFd];
__device__ __nv_bfloat16 g_Ahi[ROWS*FFd];
__device__ __nv_bfloat16 g_Alo[ROWS*FFd];
__device__ __nv_bfloat16 g_Bhi [FFd*Dd];
__device__ __nv_bfloat16 g_Blo [FFd*Dd];
__device__ __nv_bfloat16 g_B2hi[FFd*Dd];
__device__ __nv_bfloat16 g_B2lo[FFd*Dd];
__device__ __nv_bfloat16 g_B3hi[FFd*Dd];
__device__ __nv_bfloat16 g_B3lo[FFd*Dd];
__device__ __nv_bfloat16 g_Shi[ROWS*FFd];
__device__ __nv_bfloat16 g_Slo[ROWS*FFd];
__device__ __nv_bfloat16 g_fQh[ROWS*Dd];
__device__ __nv_bfloat16 g_fQl[ROWS*Dd];
__device__ __nv_bfloat16 g_fKh[ROWS*Dd];
__device__ __nv_bfloat16 g_fKl[ROWS*Dd];
__device__ __nv_bfloat16 g_fVh[ROWS*Dd];
__device__ __nv_bfloat16 g_fVl[ROWS*Dd];

// ================= helpers =================
__device__ __forceinline__ uint32_t smem_u32(const void* p) {
    uint32_t a;
    asm("{ .reg .u64 t; cvta.to.shared.u64 t, %1; cvt.u32.u64 %0, t; }"
        : "=r"(a) : "l"(p));
    return a;
}

#define SW128(o) ((o) ^ (((o) >> 3) & 0x70))

static constexpr uint64_t DESC_BASE_SW128 =
    (uint64_t(2)  << 61) | (uint64_t(1) << 46) | (uint64_t(64) << 32) | (uint64_t(1) << 16);

#define MMA_IDESC_CG2 0x10400490u   /* M=256, N=256 */
#define MMA_IDESC_QK  0x08100490u   /* M=128, N=64  */
#define MMA_IDESC_PV  0x08200490u   /* M=128, N=128 */

__device__ __forceinline__ void split1(float v, __nv_bfloat16& h, __nv_bfloat16& l) {
    h = __float2bfloat16(v);
    l = __float2bfloat16(v - __bfloat162float(h));
}
__device__ __forceinline__ void split2(float a, float b, uint32_t& hw, uint32_t& lw) {
    __nv_bfloat162 h = __floats2bfloat162_rn(a, b);
    float la = a - __bfloat162float(__low2bfloat16(h));
    float lb = b - __bfloat162float(__high2bfloat16(h));
    __nv_bfloat162 l = __floats2bfloat162_rn(la, lb);
    hw = *reinterpret_cast<uint32_t*>(&h);
    lw = *reinterpret_cast<uint32_t*>(&l);
}

#if HAS_TCGEN05
__device__ __forceinline__ uint64_t mkdesc(uint32_t addr) {
    return DESC_BASE_SW128 | ((uint64_t)(addr >> 4) & 0x3FFF);
}
__device__ __forceinline__ void mma_bf16_ss_cg2(uint32_t d, uint64_t ad, uint64_t bd, uint32_t en) {
    asm volatile(
        "{\n\t.reg .pred p;\n\tsetp.ne.u32 p, %4, 0;\n\t"
        "tcgen05.mma.cta_group::2.kind::f16 [%0], %1, %2, %3, {%5,%5,%5,%5,%5,%5,%5,%5}, p;\n\t}"
        :: "r"(d), "l"(ad), "l"(bd), "r"(MMA_IDESC_CG2), "r"(en), "r"(0u) : "memory");
}
__device__ __forceinline__ void mma_ss_cg1(uint32_t d, uint64_t ad, uint64_t bd,
                                           uint32_t idesc, uint32_t en) {
    asm volatile(
        "{\n\t.reg .pred p;\n\tsetp.ne.u32 p, %4, 0;\n\t"
        "tcgen05.mma.cta_group::1.kind::f16 [%0], %1, %2, %3, {%5,%5,%5,%5}, p;\n\t}"
        :: "r"(d), "l"(ad), "l"(bd), "r"(idesc), "r"(en), "r"(0u) : "memory");
}
__device__ __forceinline__ void mbar_init(uint32_t m, uint32_t cnt) {
    asm volatile("mbarrier.init.shared.b64 [%0], %1;" :: "r"(m), "r"(cnt) : "memory");
}
__device__ __forceinline__ void mbar_wait(uint32_t m, uint32_t parity) {
    asm volatile(
        "{\n\t.reg .pred P1;\n"
        "W%=:\n\t"
        "mbarrier.try_wait.parity.acquire.cta.shared::cta.b64 P1, [%0], %1, 0x989680;\n\t"
        "@P1 bra.uni D%=;\n\t"
        "bra.uni W%=;\n"
        "D%=:\n\t}"
        :: "r"(m), "r"(parity) : "memory");
}
__device__ __forceinline__ void tc_commit_cg1(uint32_t m) {
    asm volatile("tcgen05.commit.cta_group::1.mbarrier::arrive::one.shared::cluster.b64 [%0];"
                 :: "r"(m) : "memory");
}
__device__ __forceinline__ void tc_commit_mc2(uint32_t m) {
    asm volatile(
        "tcgen05.commit.cta_group::2.mbarrier::arrive::one.shared::cluster.multicast::cluster.b64 [%0], %1;"
        :: "r"(m), "h"((uint16_t)0x3) : "memory");
}
__device__ __forceinline__ void mbar_arrive_rank0(uint32_t local_addr) {
    asm volatile(
        "{\n\t.reg .b32 ra;\n\t"
        "mapa.shared::cluster.u32 ra, %0, %1;\n\t"
        "mbarrier.arrive.shared::cluster.b64 _, [ra];\n\t}"
        :: "r"(local_addr), "r"(0) : "memory");
}
__device__ __forceinline__ void ldtm32(uint32_t* r, uint32_t a) {
    asm volatile(
        "tcgen05.ld.sync.aligned.32x32b.x32.b32 "
        "{%0,%1,%2,%3,%4,%5,%6,%7,%8,%9,%10,%11,%12,%13,%14,%15,"
        "%16,%17,%18,%19,%20,%21,%22,%23,%24,%25,%26,%27,%28,%29,%30,%31}, [%32];"
        : "=r"(r[0]),"=r"(r[1]),"=r"(r[2]),"=r"(r[3]),"=r"(r[4]),"=r"(r[5]),"=r"(r[6]),"=r"(r[7]),
          "=r"(r[8]),"=r"(r[9]),"=r"(r[10]),"=r"(r[11]),"=r"(r[12]),"=r"(r[13]),"=r"(r[14]),"=r"(r[15]),
          "=r"(r[16]),"=r"(r[17]),"=r"(r[18]),"=r"(r[19]),"=r"(r[20]),"=r"(r[21]),"=r"(r[22]),"=r"(r[23]),
          "=r"(r[24]),"=r"(r[25]),"=r"(r[26]),"=r"(r[27]),"=r"(r[28]),"=r"(r[29]),"=r"(r[30]),"=r"(r[31])
        : "r"(a));
}
__device__ __forceinline__ void sttm32(uint32_t a, const uint32_t* r) {
    asm volatile(
        "tcgen05.st.sync.aligned.32x32b.x32.b32 [%32], "
        "{%0,%1,%2,%3,%4,%5,%6,%7,%8,%9,%10,%11,%12,%13,%14,%15,"
        "%16,%17,%18,%19,%20,%21,%22,%23,%24,%25,%26,%27,%28,%29,%30,%31};"
        :: "r"(r[0]),"r"(r[1]),"r"(r[2]),"r"(r[3]),"r"(r[4]),"r"(r[5]),"r"(r[6]),"r"(r[7]),
           "r"(r[8]),"r"(r[9]),"r"(r[10]),"r"(r[11]),"r"(r[12]),"r"(r[13]),"r"(r[14]),"r"(r[15]),
           "r"(r[16]),"r"(r[17]),"r"(r[18]),"r"(r[19]),"r"(r[20]),"r"(r[21]),"r"(r[22]),"r"(r[23]),
           "r"(r[24]),"r"(r[25]),"r"(r[26]),"r"(r[27]),"r"(r[28]),"r"(r[29]),"r"(r[30]),"r"(r[31]),
           "r"(a)
        : "memory");
}
__device__ __forceinline__ void cpasync16(uint32_t dst, const void* src) {
    asm volatile("cp.async.cg.shared.global [%0], [%1], 16;" :: "r"(dst), "l"(src) : "memory");
}
__device__ __forceinline__ void cp_arrive(uint32_t m) {
    asm volatile("cp.async.mbarrier.arrive.noinc.shared.b64 [%0];" :: "r"(m) : "memory");
}
#define CP_COMMIT() asm volatile("cp.async.commit_group;" ::: "memory")
#define CP_WAIT0()  asm volatile("cp.async.wait_group 0;" ::: "memory")
#define TC_WAIT_LD() asm volatile("tcgen05.wait::ld.sync.aligned;" ::: "memory")
#define TC_WAIT_ST() asm volatile("tcgen05.wait::st.sync.aligned;" ::: "memory")
#define TC_FENCE_BEFORE() asm volatile("tcgen05.fence::before_thread_sync;" ::: "memory")
#define TC_FENCE_AFTER()  asm volatile("tcgen05.fence::after_thread_sync;" ::: "memory")
#define CLUSTER_SYNC() do { \
    asm volatile("barrier.cluster.arrive.aligned;" ::: "memory"); \
    asm volatile("barrier.cluster.wait.aligned;" ::: "memory"); \
} while (0)
#endif  // HAS_TCGEN05

// ---------------- split fp32 -> bf16 hi/lo (8 elems/thread, 16B ld/st) ----------------
__global__ void __launch_bounds__(256) split_kernel(const float* __restrict__ src,
                                                    __nv_bfloat16* __restrict__ hi,
                                                    __nv_bfloat16* __restrict__ lo,
                                                    int n8)
{
    int idx = blockIdx.x * blockDim.x + threadIdx.x;
    if (idx >= n8) return;
    float4 a = ((const float4*)src)[2 * idx];
    float4 b = ((const float4*)src)[2 * idx + 1];
    uint4 H, L;
    split2(a.x, a.y, H.x, L.x);
    split2(a.z, a.w, H.y, L.y);
    split2(b.x, b.y, H.z, L.z);
    split2(b.z, b.w, H.w, L.w);
    ((uint4*)hi)[idx] = H;
    ((uint4*)lo)[idx] = L;
}

// ---------------- LayerNorm emitting bf16 hi/lo directly ----------------
__global__ void __launch_bounds__(256) ln_split_kernel(const float* __restrict__ x,
                                                       const float* __restrict__ g,
                                                       const float* __restrict__ b,
                                                       __nv_bfloat16* __restrict__ hi,
                                                       __nv_bfloat16* __restrict__ lo)
{
    const int row = blockIdx.x;
    const int tid = threadIdx.x;
    const float* xr = x + (size_t)row * Dd;
    __shared__ float red[256];

    float s = 0.f;
    for (int i = tid; i < Dd; i += 256) s += xr[i];
    red[tid] = s; __syncthreads();
    for (int off = 128; off > 0; off >>= 1) {
        if (tid < off) red[tid] += red[tid + off];
        __syncthreads();
    }
    const float mean = red[0] * (1.f / Dd);
    __syncthreads();

    float v = 0.f;
    for (int i = tid; i < Dd; i += 256) { float d = xr[i] - mean; v += d * d; }
    red[tid] = v; __syncthreads();
    for (int off = 128; off > 0; off >>= 1) {
        if (tid < off) red[tid] += red[tid + off];
        __syncthreads();
    }
    const float rstd = rsqrtf(red[0] * (1.f / Dd) + 1e-5f);

    const int i = tid * 8;
    float4 xa = *(const float4*)(xr + i);
    float4 xb = *(const float4*)(xr + i + 4);
    float4 ga = *(const float4*)(g + i);
    float4 gb = *(const float4*)(g + i + 4);
    float4 ba = *(const float4*)(b + i);
    float4 bb = *(const float4*)(b + i + 4);
    float v0 = (xa.x - mean) * rstd * ga.x + ba.x;
    float v1 = (xa.y - mean) * rstd * ga.y + ba.y;
    float v2 = (xa.z - mean) * rstd * ga.z + ba.z;
    float v3 = (xa.w - mean) * rstd * ga.w + ba.w;
    float v4 = (xb.x - mean) * rstd * gb.x + bb.x;
    float v5 = (xb.y - mean) * rstd * gb.y + bb.y;
    float v6 = (xb.z - mean) * rstd * gb.z + bb.z;
    float v7 = (xb.w - mean) * rstd * gb.w + bb.w;
    uint4 H, L;
    split2(v0, v1, H.x, L.x);
    split2(v2, v3, H.y, L.y);
    split2(v4, v5, H.z, L.z);
    split2(v6, v7, H.w, L.w);
    ((uint4*)(hi + (size_t)row * Dd))[tid] = H;
    ((uint4*)(lo + (size_t)row * Dd))[tid] = L;
}

// ---------------- V transpose+split ----------------
__global__ void __launch_bounds__(256) vtrans_kernel(const float* __restrict__ v,
                                                     __nv_bfloat16* __restrict__ Vth,
                                                     __nv_bfloat16* __restrict__ Vtl)
{
    __shared__ float tile[32][65];
    const int bh = blockIdx.z;
    const int b  = bh >> 4, h = bh & 15;
    const int t0 = blockIdx.x * 64;
    const int d0 = blockIdx.y * 32;
    const int x = threadIdx.x, y = threadIdx.y;  // (32,8)
#pragma unroll
    for (int i = 0; i < 8; i++) {
        const int tt = y + i * 8;
        tile[x][tt] = v[(size_t)(b * Tt + t0 + tt) * Dd + h * HDd + d0 + x];
    }
    __syncthreads();
#pragma unroll
    for (int i = 0; i < 4; i++) {
        const int hdl = y + i * 8;
        const float v0 = tile[hdl][x * 2];
        const float v1 = tile[hdl][x * 2 + 1];
        uint32_t hw, lw;
        split2(v0, v1, hw, lw);
        const size_t idx = (size_t)(bh * HDd + d0 + hdl) * Tt + t0 + x * 2;
        *(uint32_t*)(Vth + idx) = hw;
        *(uint32_t*)(Vtl + idx) = lw;
    }
}

// ============ GEMM core macros (shared by generic and merged-QKV kernels) ============
#define NSTAGE 3
#define STAGE_BYTES 65536
#define GEMM_SMEM (1024 + NSTAGE * STAGE_BYTES)
#define GEMM_THREADS 288

#if HAS_TCGEN05
// common prologue+mainloop; leaves tmem/tile_abs set and all MMAs complete.
#define GEMM_CORE(AhP, AlP, BhP, BlP, KK)                                               \
    const uint32_t sbase = smem_u32(smem);                                              \
    const int tid  = threadIdx.x;                                                       \
    const int wid  = tid >> 5;                                                          \
    const int lane = tid & 31;                                                          \
    const int rank = blockIdx.x & 1;                                                    \
    const uint32_t tile_abs = (sbase + 128 + 1023) & ~1023u;                            \
    const uint32_t mb_full  = sbase + 8;                                                \
    const uint32_t mb_f2    = sbase + 32;                                               \
    const uint32_t mb_empty = sbase + 56;                                               \
    if (wid == 0) {                                                                     \
        asm volatile("tcgen05.alloc.cta_group::2.sync.aligned.shared::cta.b32 [%0], %1;"\
                     :: "r"(sbase), "r"(256u) : "memory");                              \
        asm volatile("tcgen05.relinquish_alloc_permit.cta_group::2.sync.aligned;");     \
    }                                                                                   \
    if (tid == 0) {                                                                     \
        for (int s = 0; s < NSTAGE; s++) {                                              \
            mbar_init(mb_full  + s * 8, 256);                                           \
            mbar_init(mb_f2    + s * 8, 2);                                             \
            mbar_init(mb_empty + s * 8, 1);                                             \
        }                                                                               \
    }                                                                                   \
    __syncthreads();                                                                    \
    CLUSTER_SYNC();                                                                     \
    uint32_t tmem;                                                                      \
    asm volatile("ld.shared.b32 %0, [%1];" : "=r"(tmem) : "r"(sbase));                  \
    const int n = (KK) >> 6;                                                            \
    if (tid < 256) {                                                                    \
        const int r  = tid >> 1;                                                        \
        const int hh = tid & 1;                                                         \
        const uint32_t off = r * 128 + hh * 64;                                         \
        const __nv_bfloat16* AgH = (AhP) + (size_t)(bm + rank * 128 + r) * (KK) + hh * 32; \
        const __nv_bfloat16* AgL = (AlP) + (size_t)(bm + rank * 128 + r) * (KK) + hh * 32; \
        const __nv_bfloat16* BgH = (BhP) + (size_t)(bnl + rank * 128 + r) * (KK) + hh * 32; \
        const __nv_bfloat16* BgL = (BlP) + (size_t)(bnl + rank * 128 + r) * (KK) + hh * 32; \
        for (int c = 0; c < n; c++) {                                                   \
            const int s = c % NSTAGE;                                                   \
            const int use = c / NSTAGE;                                                 \
            if (c >= NSTAGE) mbar_wait(mb_empty + s * 8, (use - 1) & 1);                \
            const uint32_t sb = tile_abs + s * STAGE_BYTES;                             \
            const size_t kof = (size_t)c * 64;                                          \
            _Pragma("unroll")                                                           \
            for (int j = 0; j < 4; j++) {                                               \
                const uint32_t o = SW128(off + j * 16);                                 \
                cpasync16(sb + o,         AgH + kof + j * 8);                           \
                cpasync16(sb + 16384 + o, AgL + kof + j * 8);                           \
                cpasync16(sb + 32768 + o, BgH + kof + j * 8);                           \
                cpasync16(sb + 49152 + o, BgL + kof + j * 8);                           \
            }                                                                           \
            cp_arrive(mb_full + s * 8);                                                 \
        }                                                                               \
    } else if (tid == 256) {                                                            \
        for (int i = 0; i < n; i++) {                                                   \
            const int si = i % NSTAGE;                                                  \
            mbar_wait(mb_full + si * 8, (i / NSTAGE) & 1);                              \
            mbar_arrive_rank0(mb_f2 + si * 8);                                          \
            if (rank == 0) {                                                            \
                mbar_wait(mb_f2 + si * 8, (i / NSTAGE) & 1);                            \
                asm volatile("fence.proxy.async.shared::cta;" ::: "memory");            \
                const uint32_t sbi = tile_abs + si * STAGE_BYTES;                       \
                const uint64_t ah = mkdesc(sbi);                                        \
                const uint64_t al = mkdesc(sbi + 16384);                                \
                const uint64_t bh = mkdesc(sbi + 32768);                                \
                const uint64_t bl = mkdesc(sbi + 49152);                                \
                _Pragma("unroll")                                                       \
                for (int k = 0; k < 4; k++)                                             \
                    mma_bf16_ss_cg2(tmem, ah + k * 2, bh + k * 2, (i > 0 || k > 0) ? 1u : 0u); \
                _Pragma("unroll")                                                       \
                for (int k = 0; k < 4; k++)                                             \
                    mma_bf16_ss_cg2(tmem, ah + k * 2, bl + k * 2, 1u);                  \
                _Pragma("unroll")                                                       \
                for (int k = 0; k < 4; k++)                                             \
                    mma_bf16_ss_cg2(tmem, al + k * 2, bh + k * 2, 1u);                  \
                tc_commit_mc2(mb_empty + si * 8);                                       \
            }                                                                           \
        }                                                                               \
    }                                                                                   \
    {                                                                                   \
        const int i = n - 1, si = i % NSTAGE;                                           \
        mbar_wait(mb_empty + si * 8, (i / NSTAGE) & 1);                                 \
    }                                                                                   \
    TC_FENCE_AFTER();

#define GEMM_DEALLOC()                                                                  \
    __syncthreads();                                                                    \
    if (wid == 0) {                                                                     \
        asm volatile("tcgen05.dealloc.cta_group::2.sync.aligned.b32 %0, %1;"            \
                     :: "r"(tmem), "r"(256u));                                          \
    }                                                                                   \
    CLUSTER_SYNC();
#endif  // HAS_TCGEN05

// ============ generic cg2 GEMM (plain / silu+split epilogues) ============
__global__ void __launch_bounds__(GEMM_THREADS, 1) __cluster_dims__(2, 1, 1)
mma_gemm_kernel(const __nv_bfloat16* __restrict__ Ah, const __nv_bfloat16* __restrict__ Al,
                const __nv_bfloat16* __restrict__ Bh, const __nv_bfloat16* __restrict__ Bl,
                const float* __restrict__ bias, const float* __restrict__ resid,
                float* __restrict__ C,
                const float* __restrict__ gate,
                __nv_bfloat16* __restrict__ Chi, __nv_bfloat16* __restrict__ Clo,
                int M, int N, int K)
{
    extern __shared__ char smem[];
#if HAS_TCGEN05
    const int bm  = blockIdx.y * 256;
    const int bnl = (blockIdx.x >> 1) * 256;

    GEMM_CORE(Ah, Al, Bh, Bl, K)

    if (wid < 8) {
        const int sub  = wid & 3;
        const int half = wid >> 2;
        const int row  = bm + rank * 128 + sub * 32 + lane;
        const float* rrow = resid ? resid + (size_t)row * N : nullptr;
        const float* grow = gate ? gate + (size_t)row * N : nullptr;
        float* crow = C ? C + (size_t)row * N : nullptr;
#pragma unroll 1
        for (int half2 = 0; half2 < 2; half2++) {
#pragma unroll 1
            for (int c32 = 0; c32 < 2; c32++) {
                uint32_t d[32];
                ldtm32(d, tmem + half2 * 128 + half * 64 + c32 * 32);
                TC_WAIT_LD();
                const int col0 = bnl + half2 * 128 + half * 64 + c32 * 32;
                if (grow) {
                    uint2* hrow = (uint2*)(Chi + (size_t)row * N + col0);
                    uint2* lrow = (uint2*)(Clo + (size_t)row * N + col0);
#pragma unroll
                    for (int t2 = 0; t2 < 8; t2++) {
                        const int c = col0 + t2 * 4;
                        float4 gv = *(const float4*)(grow + c);
                        const float u0 = __uint_as_float(d[t2 * 4 + 0]) + bias[c + 0];
                        const float u1 = __uint_as_float(d[t2 * 4 + 1]) + bias[c + 1];
                        const float u2 = __uint_as_float(d[t2 * 4 + 2]) + bias[c + 2];
                        const float u3 = __uint_as_float(d[t2 * 4 + 3]) + bias[c + 3];
                        const float v0 = gv.x / (1.f + __expf(-gv.x)) * u0;
                        const float v1 = gv.y / (1.f + __expf(-gv.y)) * u1;
                        const float v2 = gv.z / (1.f + __expf(-gv.z)) * u2;
                        const float v3 = gv.w / (1.f + __expf(-gv.w)) * u3;
                        uint2 hv, lv;
                        split2(v0, v1, hv.x, lv.x);
                        split2(v2, v3, hv.y, lv.y);
                        hrow[t2] = hv;
                        lrow[t2] = lv;
                    }
                } else if (rrow) {
#pragma unroll
                    for (int j = 0; j < 32; j++)
                        crow[col0 + j] = __uint_as_float(d[j]) + bias[col0 + j] + rrow[col0 + j];
                } else {
#pragma unroll
                    for (int j = 0; j < 32; j++)
                        crow[col0 + j] = __uint_as_float(d[j]) + bias[col0 + j];
                }
            }
        }
    }
    GEMM_DEALLOC()
#else
    float* As = (float*)smem;
    float* Bs = As + 8 * 128;
    const int tid = threadIdx.x;
    const int rank = blockIdx.x & 1;
    const int bm = blockIdx.y * 256 + rank * 128;
    const int bn0 = (blockIdx.x >> 1) * 256;
    const int lr  = tid >> 1;
    const int lcc = (tid & 1) * 4;
    const int tx = tid & 15, ty = tid >> 4;

    for (int h = 0; h < 2; h++) {
        const int bn = bn0 + h * 128;
        float acc[8][8];
#pragma unroll
        for (int i = 0; i < 8; i++)
#pragma unroll
            for (int j = 0; j < 8; j++) acc[i][j] = 0.f;

        for (int k0 = 0; k0 < K; k0 += 8) {
            if (tid < 256) {
                const __nv_bfloat16* aph = Ah + (size_t)(bm + lr) * K + k0 + lcc;
                const __nv_bfloat16* apl = Al + (size_t)(bm + lr) * K + k0 + lcc;
                const __nv_bfloat16* bph = Bh + (size_t)(bn + lr) * K + k0 + lcc;
                const __nv_bfloat16* bpl = Bl + (size_t)(bn + lr) * K + k0 + lcc;
#pragma unroll
                for (int j = 0; j < 4; j++) {
                    As[(lcc + j) * 128 + lr] = __bfloat162float(aph[j]) + __bfloat162float(apl[j]);
                    Bs[(lcc + j) * 128 + lr] = __bfloat162float(bph[j]) + __bfloat162float(bpl[j]);
                }
            }
            __syncthreads();
            if (tid < 256) {
#pragma unroll
                for (int kk = 0; kk < 8; kk++) {
                    float a[8], bb[8];
#pragma unroll
                    for (int i = 0; i < 8; i++)
                        a[i] = As[kk * 128 + ((i & 4) << 4) + ty * 4 + (i & 3)];
#pragma unroll
                    for (int j = 0; j < 8; j++)
                        bb[j] = Bs[kk * 128 + ((j & 4) << 4) + tx * 4 + (j & 3)];
#pragma unroll
                    for (int i = 0; i < 8; i++)
#pragma unroll
                        for (int j = 0; j < 8; j++)
                            acc[i][j] += a[i] * bb[j];
                }
            }
            __syncthreads();
        }

        if (tid < 256) {
#pragma unroll
            for (int i = 0; i < 8; i++) {
                const int row = bm + ((i & 4) << 4) + ty * 4 + (i & 3);
                if (gate) {
#pragma unroll
                    for (int j = 0; j < 8; j++) {
                        const int c = bn + ((j & 4) << 4) + tx * 4 + (j & 3);
                        float gvv = gate[(size_t)row * N + c];
                        float u = acc[i][j] + bias[c];
                        float vv = gvv / (1.f + __expf(-gvv)) * u;
                        __nv_bfloat16 hh, ll;
                        split1(vv, hh, ll);
                        Chi[(size_t)row * N + c] = hh; Clo[(size_t)row * N + c] = ll;
                    }
                } else {
#pragma unroll
                    for (int j = 0; j < 8; j++) {
                        const int col = bn + ((j & 4) << 4) + tx * 4 + (j & 3);
                        float vv = acc[i][j] + bias[col];
                        if (resid) vv += resid[(size_t)row * N + col];
                        C[(size_t)row * N + col] = vv;
                    }
                }
            }
        }
    }
#endif
}

// ============ merged QKV GEMM: one launch, operand selected by bn/2048 ============
// Q,K epilogues: rope+split -> fQ/fK.  V epilogue: fp32 v.
__global__ void __launch_bounds__(GEMM_THREADS, 1) __cluster_dims__(2, 1, 1)
mma_qkv_kernel(const __nv_bfloat16* __restrict__ Ah, const __nv_bfloat16* __restrict__ Al,
               const __nv_bfloat16* __restrict__ B1h, const __nv_bfloat16* __restrict__ B1l,
               const __nv_bfloat16* __restrict__ B2h, const __nv_bfloat16* __restrict__ B2l,
               const __nv_bfloat16* __restrict__ B3h, const __nv_bfloat16* __restrict__ B3l,
               const float* __restrict__ bq, const float* __restrict__ bk,
               const float* __restrict__ bv,
               const float* __restrict__ rope,
               __nv_bfloat16* __restrict__ Qh, __nv_bfloat16* __restrict__ Ql,
               __nv_bfloat16* __restrict__ Kh, __nv_bfloat16* __restrict__ Kl,
               float* __restrict__ V)
{
    extern __shared__ char smem[];
    const int K = Dd, N = Dd;
#if HAS_TCGEN05
    const int bm  = blockIdx.y * 256;
    const int bng = (blockIdx.x >> 1) * 256;   // global [0, 3*Dd)
    const int sel = bng >> 11;                 // /2048
    const int bnl = bng & 2047;
    const __nv_bfloat16* Bh = (sel == 0) ? B1h : (sel == 1) ? B2h : B3h;
    const __nv_bfloat16* Bl = (sel == 0) ? B1l : (sel == 1) ? B2l : B3l;
    const float* bias = (sel == 0) ? bq : (sel == 1) ? bk : bv;

    GEMM_CORE(Ah, Al, Bh, Bl, K)

    if (wid < 8) {
        const int sub  = wid & 3;
        const int half = wid >> 2;
        const int row  = bm + rank * 128 + sub * 32 + lane;
        __nv_bfloat16* Ohi = (sel == 0) ? Qh : Kh;
        __nv_bfloat16* Olo = (sel == 0) ? Ql : Kl;
#pragma unroll 1
        for (int half2 = 0; half2 < 2; half2++) {
#pragma unroll 1
            for (int c32 = 0; c32 < 2; c32++) {
                uint32_t d[32];
                ldtm32(d, tmem + half2 * 128 + half * 64 + c32 * 32);
                TC_WAIT_LD();
                const int col0 = bnl + half2 * 128 + half * 64 + c32 * 32;
                if (sel < 2) {
                    uint2* hrow = (uint2*)(Ohi + (size_t)row * N + col0);
                    uint2* lrow = (uint2*)(Olo + (size_t)row * N + col0);
#pragma unroll
                    for (int t2 = 0; t2 < 8; t2++) {
                        const int c = col0 + t2 * 4;
                        const float a0 = __uint_as_float(d[t2 * 4 + 0]) + bias[c + 0];
                        const float b0 = __uint_as_float(d[t2 * 4 + 1]) + bias[c + 1];
                        const float a1 = __uint_as_float(d[t2 * 4 + 2]) + bias[c + 2];
                        const float b1 = __uint_as_float(d[t2 * 4 + 3]) + bias[c + 3];
                        const float cr0 = rope[c + 0], ci0 = rope[c + 1];
                        const float cr1 = rope[c + 2], ci1 = rope[c + 3];
                        uint2 hv, lv;
                        split2(a0 * cr0 - b0 * ci0, a0 * ci0 + b0 * cr0, hv.x, lv.x);
                        split2(a1 * cr1 - b1 * ci1, a1 * ci1 + b1 * cr1, hv.y, lv.y);
                        hrow[t2] = hv;
                        lrow[t2] = lv;
                    }
                } else {
                    float* crow = V + (size_t)row * N;
#pragma unroll
                    for (int j = 0; j < 32; j++)
                        crow[col0 + j] = __uint_as_float(d[j]) + bias[col0 + j];
                }
            }
        }
    }
    GEMM_DEALLOC()
#else
    float* As = (float*)smem;
    float* Bs = As + 8 * 128;
    const int tid = threadIdx.x;
    const int rank = blockIdx.x & 1;
    const int bm = blockIdx.y * 256 + rank * 128;
    const int bng = (blockIdx.x >> 1) * 256;
    const int sel = bng >> 11;
    const int bn0 = bng & 2047;
    const __nv_bfloat16* Bh = (sel == 0) ? B1h : (sel == 1) ? B2h : B3h;
    const __nv_bfloat16* Bl = (sel == 0) ? B1l : (sel == 1) ? B2l : B3l;
    const float* bias = (sel == 0) ? bq : (sel == 1) ? bk : bv;
    const int lr  = tid >> 1;
    const int lcc = (tid & 1) * 4;
    const int tx = tid & 15, ty = tid >> 4;

    for (int h = 0; h < 2; h++) {
        const int bn = bn0 + h * 128;
        float acc[8][8];
#pragma unroll
        for (int i = 0; i < 8; i++)
#pragma unroll
            for (int j = 0; j < 8; j++) acc[i][j] = 0.f;

        for (int k0 = 0; k0 < K; k0 += 8) {
            if (tid < 256) {
                const __nv_bfloat16* aph = Ah + (size_t)(bm + lr) * K + k0 + lcc;
                const __nv_bfloat16* apl = Al + (size_t)(bm + lr) * K + k0 + lcc;
                const __nv_bfloat16* bph = Bh + (size_t)(bn + lr) * K + k0 + lcc;
                const __nv_bfloat16* bpl = Bl + (size_t)(bn + lr) * K + k0 + lcc;
#pragma unroll
                for (int j = 0; j < 4; j++) {
                    As[(lcc + j) * 128 + lr] = __bfloat162float(aph[j]) + __bfloat162float(apl[j]);
                    Bs[(lcc + j) * 128 + lr] = __bfloat162float(bph[j]) + __bfloat162float(bpl[j]);
                }
            }
            __syncthreads();
            if (tid < 256) {
#pragma unroll
                for (int kk = 0; kk < 8; kk++) {
                    float a[8], bb[8];
#pragma unroll
                    for (int i = 0; i < 8; i++)
                        a[i] = As[kk * 128 + ((i & 4) << 4) + ty * 4 + (i & 3)];
#pragma unroll
                    for (int j = 0; j < 8; j++)
                        bb[j] = Bs[kk * 128 + ((j & 4) << 4) + tx * 4 + (j & 3)];
#pragma unroll
                    for (int i = 0; i < 8; i++)
#pragma unroll
                        for (int j = 0; j < 8; j++)
                            acc[i][j] += a[i] * bb[j];
                }
            }
            __syncthreads();
        }

        if (tid < 256) {
#pragma unroll
            for (int i = 0; i < 8; i++) {
                const int row = bm + ((i & 4) << 4) + ty * 4 + (i & 3);
                if (sel < 2) {
                    __nv_bfloat16* Ohi = (sel == 0) ? Qh : Kh;
                    __nv_bfloat16* Olo = (sel == 0) ? Ql : Kl;
#pragma unroll
                    for (int j = 0; j < 8; j += 2) {
                        const int c = bn + ((j & 4) << 4) + tx * 4 + (j & 3);
                        float a0 = acc[i][j] + bias[c];
                        float b0 = acc[i][j + 1] + bias[c + 1];
                        float r0 = a0 * rope[c] - b0 * rope[c + 1];
                        float r1 = a0 * rope[c + 1] + b0 * rope[c];
                        __nv_bfloat16 hh, ll;
                        split1(r0, hh, ll);
                        Ohi[(size_t)row * N + c] = hh; Olo[(size_t)row * N + c] = ll;
                        split1(r1, hh, ll);
                        Ohi[(size_t)row * N + c + 1] = hh; Olo[(size_t)row * N + c + 1] = ll;
                    }
                } else {
#pragma unroll
                    for (int j = 0; j < 8; j++) {
                        const int col = bn + ((j & 4) << 4) + tx * 4 + (j & 3);
                        V[(size_t)row * N + col] = acc[i][j] + bias[col];
                    }
                }
            }
        }
    }
#endif
}

// ============ tcgen05 flash attention (unchanged, passing) ============
#define FLASH_SMEM (1024 + 160 * 1024 + 1024)

__global__ void __launch_bounds__(256, 1) flash_mma_kernel(
    const __nv_bfloat16* __restrict__ Qh, const __nv_bfloat16* __restrict__ Ql,
    const __nv_bfloat16* __restrict__ Kh, const __nv_bfloat16* __restrict__ Kl,
    const __nv_bfloat16* __restrict__ Vh, const __nv_bfloat16* __restrict__ Vl,
    __nv_bfloat16* __restrict__ Ohi, __nv_bfloat16* __restrict__ Olo)
{
    extern __shared__ char smem[];
#if HAS_TCGEN05
    const uint32_t sbase = smem_u32(smem);
    const int tid  = threadIdx.x;
    const int wid  = tid >> 5;
    const int lane = tid & 31;
    const int qb = gridDim.x - 1 - blockIdx.x;
    const int h = blockIdx.y, b = blockIdx.z;
    const int q0 = qb * 128;

    const uint32_t mb_qk = sbase + 8;
    const uint32_t mb_pv = sbase + 16;
    int*   flags  = (int*)(smem + 24);
    float* redbuf = (float*)(smem + 64);
    const uint32_t tile_abs = (sbase + 576 + 1023) & ~1023u;
    const uint32_t tile_off = tile_abs - sbase;

    if (wid == 0) {
        asm volatile("tcgen05.alloc.cta_group::1.sync.aligned.shared::cta.b32 [%0], %1;"
                     :: "r"(sbase), "r"(256u) : "memory");
        asm volatile("tcgen05.relinquish_alloc_permit.cta_group::1.sync.aligned;");
    }
    if (tid == 0) { mbar_init(mb_qk, 1); mbar_init(mb_pv, 1); }
    __syncthreads();
    uint32_t tmem;
    asm volatile("ld.shared.b32 %0, [%1];" : "=r"(tmem) : "r"(sbase));
    const uint32_t tm_S = tmem;
    const uint32_t tm_O = tmem + 64;

#pragma unroll
    for (int i = 0; i < 2; i++) {
        int u = tid * 2 + i;
        int buf = u >> 8, rem = u & 255, half = rem >> 7, row = rem & 127;
        const __nv_bfloat16* src = (buf ? Ql : Qh)
            + (size_t)(b * Tt + q0 + row) * Dd + h * HDd + half * 64;
        uint32_t dst = tile_abs + buf * 32768 + half * 16384;
        uint32_t off = row * 128;
#pragma unroll
        for (int j = 0; j < 8; j++)
            cpasync16(dst + SW128(off + j * 16), src + j * 8);
    }
    CP_COMMIT();

    const int sw   = wid & 3;
    const int colh = wid >> 2;
    const int row  = sw * 32 + lane;
    const float scale = 0.088388347648318447f;

    float m = -1e30f, l = 0.f;
    const int nt = 2 * qb + 2;

    for (int t = 0; t < nt; t++) {
        const int j0 = t * 64;
        if (t > 0) mbar_wait(mb_pv, (t - 1) & 1);

#pragma unroll
        for (int i = 0; i < 2; i++) {
            int u = tid * 2 + i;
            const __nv_bfloat16* src;
            uint32_t dst, off;
            if (u < 256) {
                int kr = u & 63, half = (u >> 6) & 1, buf = u >> 7;
                src = (buf ? Kl : Kh) + (size_t)(b * Tt + j0 + kr) * Dd + h * HDd + half * 64;
                dst = tile_abs + 65536 + buf * 16384 + half * 8192;
                off = kr * 128;
            } else {
                int u2 = u - 256;
                int vr = u2 & 127, buf = u2 >> 7;
                src = (buf ? Vl : Vh) + (size_t)((b * Hh + h) * HDd + vr) * Tt + j0;
                dst = tile_abs + 98304 + buf * 16384;
                off = vr * 128;
            }
#pragma unroll
            for (int j = 0; j < 8; j++)
                cpasync16(dst + SW128(off + j * 16), src + j * 8);
        }
        CP_COMMIT();
        CP_WAIT0();
        __syncthreads();

        if (tid == 0) {
            asm volatile("fence.proxy.async.shared::cta;" ::: "memory");
            uint64_t qd[2][2], kd[2][2];
            qd[0][0] = mkdesc(tile_abs);          qd[0][1] = mkdesc(tile_abs + 16384);
            qd[1][0] = mkdesc(tile_abs + 32768);  qd[1][1] = mkdesc(tile_abs + 49152);
            kd[0][0] = mkdesc(tile_abs + 65536);  kd[0][1] = mkdesc(tile_abs + 73728);
            kd[1][0] = mkdesc(tile_abs + 81920);  kd[1][1] = mkdesc(tile_abs + 90112);
            int first = 1;
#pragma unroll
            for (int c3 = 0; c3 < 3; c3++) {
                const int ab = (c3 == 2) ? 1 : 0;
                const int bb = (c3 == 1) ? 1 : 0;
#pragma unroll
                for (int ks = 0; ks < 8; ks++) {
                    const int half = ks >> 2;
                    const uint64_t o = (uint64_t)((ks & 3) * 2);
                    mma_ss_cg1(tm_S, qd[ab][half] + o, kd[bb][half] + o,
                               MMA_IDESC_QK, first ? 0u : 1u);
                    first = 0;
                }
            }
            tc_commit_cg1(mb_qk);
        }
        mbar_wait(mb_qk, t & 1);
        TC_FENCE_AFTER();

        if (wid < 4) {
            uint32_t sr[64];
            ldtm32(sr,      tm_S);
            ldtm32(sr + 32, tm_S + 32);
            TC_WAIT_LD();
            float sv[64];
            float tmax = -1e30f;
#pragma unroll
            for (int c = 0; c < 64; c++) {
                float x = __uint_as_float(sr[c]) * scale;
                if (j0 + c > q0 + row) x = -1e30f;
                sv[c] = x;
                tmax = fmaxf(tmax, x);
            }
            const float mnew = fmaxf(m, tmax);
            const float alpha = __expf(m - mnew);
            m = mnew;
            float psum = 0.f;
#pragma unroll
            for (int c = 0; c < 64; c++) {
                float p = __expf(sv[c] - mnew);
                sv[c] = p;
                psum += p;
            }
            l = l * alpha + psum;
            const uint32_t prow = row * 128;
#pragma unroll
            for (int g = 0; g < 16; g++) {
                const int c = g * 4;
                uint2 hv, lv;
                split2(sv[c],     sv[c + 1], hv.x, lv.x);
                split2(sv[c + 2], sv[c + 3], hv.y, lv.y);
                const uint32_t o = SW128(prow + c * 2);
                *(uint2*)(smem + tile_off + 131072 + o) = hv;
                *(uint2*)(smem + tile_off + 147456 + o) = lv;
            }
            asm volatile("fence.proxy.async.shared::cta;" ::: "memory");
            redbuf[row] = alpha;
            unsigned bal = __ballot_sync(0xffffffffu, alpha < 0.999999f);
            if (lane == 0) flags[wid] = (bal != 0) ? 1 : 0;
        }
        __syncthreads();

        if (t > 0 && ((volatile int*)flags)[sw]) {
            const float av = ((volatile float*)redbuf)[row];
            uint32_t o0[32], o1[32];
            ldtm32(o0, tm_O + colh * 64);
            ldtm32(o1, tm_O + colh * 64 + 32);
            TC_WAIT_LD();
#pragma unroll
            for (int j = 0; j < 32; j++) {
                o0[j] = __float_as_uint(__uint_as_float(o0[j]) * av);
                o1[j] = __float_as_uint(__uint_as_float(o1[j]) * av);
            }
            sttm32(tm_O + colh * 64,      o0);
            sttm32(tm_O + colh * 64 + 32, o1);
            TC_WAIT_ST();
        }
        TC_FENCE_BEFORE();
        __syncthreads();

        if (tid == 0) {
            TC_FENCE_AFTER();
            asm volatile("fence.proxy.async.shared::cta;" ::: "memory");
            uint64_t pd[2], vd[2];
            pd[0] = mkdesc(tile_abs + 131072); pd[1] = mkdesc(tile_abs + 147456);
            vd[0] = mkdesc(tile_abs + 98304);  vd[1] = mkdesc(tile_abs + 114688);
            int first = (t == 0) ? 1 : 0;
#pragma unroll
            for (int c3 = 0; c3 < 3; c3++) {
                const int ab = (c3 == 1) ? 1 : 0;
                const int bb = (c3 == 2) ? 1 : 0;
#pragma unroll
                for (int ks = 0; ks < 4; ks++) {
                    const uint64_t o = (uint64_t)(ks * 2);
                    mma_ss_cg1(tm_O, pd[ab] + o, vd[bb] + o,
                               MMA_IDESC_PV, first ? 0u : 1u);
                    first = 0;
                }
            }
            tc_commit_cg1(mb_pv);
        }
    }

    mbar_wait(mb_pv, (nt - 1) & 1);
    TC_FENCE_AFTER();
    if (wid < 4) redbuf[row] = 1.f / l;
    __syncthreads();

    {
        const float linv = ((volatile float*)redbuf)[row];
        uint32_t o0[32], o1[32];
        ldtm32(o0, tm_O + colh * 64);
        ldtm32(o1, tm_O + colh * 64 + 32);
        TC_WAIT_LD();
        const size_t obase = (size_t)(b * Tt + q0 + row) * Dd + h * HDd + colh * 64;
        uint32_t* hrow = (uint32_t*)(Ohi + obase);
        uint32_t* lrow = (uint32_t*)(Olo + obase);
#pragma unroll
        for (int j = 0; j < 16; j++) {
            uint32_t hw, lw;
            split2(__uint_as_float(o0[2 * j]) * linv,
                   __uint_as_float(o0[2 * j + 1]) * linv, hw, lw);
            hrow[j] = hw; lrow[j] = lw;
        }
#pragma unroll
        for (int j = 0; j < 16; j++) {
            uint32_t hw, lw;
            split2(__uint_as_float(o1[2 * j]) * linv,
                   __uint_as_float(o1[2 * j + 1]) * linv, hw, lw);
            hrow[16 + j] = hw; lrow[16 + j] = lw;
        }
    }
    __syncthreads();
    if (wid == 0) {
        asm volatile("tcgen05.dealloc.cta_group::1.sync.aligned.b32 %0, %1;"
                     :: "r"(tmem), "r"(256u));
    }
#else
    const int tid = threadIdx.x;
    const int qb = gridDim.x - 1 - blockIdx.x;
    const int h = blockIdx.y, b = blockIdx.z;
    const int q0 = qb * 128;
    if (tid < 128) {
        const int rq = q0 + tid;
        float m = -1e30f, l = 0.f, o[128];
        for (int d = 0; d < 128; d++) o[d] = 0.f;
        for (int j = 0; j <= rq; j++) {
            float s = 0.f;
            const size_t qo = (size_t)(b * Tt + rq) * Dd + h * HDd;
            const size_t ko = (size_t)(b * Tt + j) * Dd + h * HDd;
            for (int d = 0; d < 128; d++) {
                float qv = __bfloat162float(Qh[qo + d]) + __bfloat162float(Ql[qo + d]);
                float kv = __bfloat162float(Kh[ko + d]) + __bfloat162float(Kl[ko + d]);
                s += qv * kv;
            }
            s *= 0.088388347648318447f;
            float mn = fmaxf(m, s);
            float al = __expf(m - mn), p = __expf(s - mn);
            m = mn;
            l = l * al + p;
            const size_t vo = (size_t)(b * Hh + h) * HDd;
            for (int d = 0; d < 128; d++) {
                float vv = __bfloat162float(Vh[(vo + d) * Tt + j]) +
                           __bfloat162float(Vl[(vo + d) * Tt + j]);
                o[d] = o[d] * al + p * vv;
            }
        }
        const size_t obase = (size_t)(b * Tt + rq) * Dd + h * HDd;
        for (int d = 0; d < 128; d++) {
            __nv_bfloat16 hi, lo;
            split1(o[d] / l, hi, lo);
            Ohi[obase + d] = hi;
            Olo[obase + d] = lo;
        }
    }
#endif
}

// ---------------- launch ----------------
extern "C" void kernel_launch(void* const* d_in, const int* in_sizes, int n_in,
                              void* d_out, int out_size)
{
    const float* x   = (const float*)d_in[0];
    const float* fr  = (const float*)d_in[1];
    const float* Wq  = (const float*)d_in[2];
    const float* bq  = (const float*)d_in[3];
    const float* Wk  = (const float*)d_in[4];
    const float* bk  = (const float*)d_in[5];
    const float* Wv  = (const float*)d_in[6];
    const float* bv  = (const float*)d_in[7];
    const float* Wo  = (const float*)d_in[8];
    const float* bo  = (const float*)d_in[9];
    const float* g1  = (const float*)d_in[10];
    const float* be1 = (const float*)d_in[11];
    const float* g2  = (const float*)d_in[12];
    const float* be2 = (const float*)d_in[13];
    const float* Wg  = (const float*)d_in[14];
    const float* bg  = (const float*)d_in[15];
    const float* Wu  = (const float*)d_in[16];
    const float* bu  = (const float*)d_in[17];
    const float* Wd  = (const float*)d_in[18];
    const float* bd  = (const float*)d_in[19];
    float* out = (float*)d_out;

    float *v, *ff1;
    __nv_bfloat16 *Ahi, *Alo, *B1h, *B1l, *B2h, *B2l, *B3h, *B3l, *Shi, *Slo;
    __nv_bfloat16 *fQh, *fQl, *fKh, *fKl, *fVh, *fVl;
    cudaGetSymbolAddress((void**)&v,    g_v);
    cudaGetSymbolAddress((void**)&ff1,  g_ff1);
    cudaGetSymbolAddress((void**)&Ahi,  g_Ahi);
    cudaGetSymbolAddress((void**)&Alo,  g_Alo);
    cudaGetSymbolAddress((void**)&B1h,  g_Bhi);
    cudaGetSymbolAddress((void**)&B1l,  g_Blo);
    cudaGetSymbolAddress((void**)&B2h,  g_B2hi);
    cudaGetSymbolAddress((void**)&B2l,  g_B2lo);
    cudaGetSymbolAddress((void**)&B3h,  g_B3hi);
    cudaGetSymbolAddress((void**)&B3l,  g_B3lo);
    cudaGetSymbolAddress((void**)&Shi,  g_Shi);
    cudaGetSymbolAddress((void**)&Slo,  g_Slo);
    cudaGetSymbolAddress((void**)&fQh,  g_fQh);
    cudaGetSymbolAddress((void**)&fQl,  g_fQl);
    cudaGetSymbolAddress((void**)&fKh,  g_fKh);
    cudaGetSymbolAddress((void**)&fKl,  g_fKl);
    cudaGetSymbolAddress((void**)&fVh,  g_fVh);
    cudaGetSymbolAddress((void**)&fVl,  g_fVl);

    cudaFuncSetAttribute(mma_gemm_kernel, cudaFuncAttributeMaxDynamicSharedMemorySize, GEMM_SMEM);
    cudaFuncSetAttribute(mma_qkv_kernel,  cudaFuncAttributeMaxDynamicSharedMemorySize, GEMM_SMEM);
    cudaFuncSetAttribute(flash_mma_kernel, cudaFuncAttributeMaxDynamicSharedMemorySize, FLASH_SMEM);

    const int DW  = Dd * Dd;     // 4M
    const int FW  = FFd * Dd;    // 16M

#define SPLIT(src, hi, lo, n) split_kernel<<<((n)/8 + 255)/256, 256>>>(src, hi, lo, (n)/8)

    // 1) LN1 -> Ahi/Alo ; split Wq/Wk/Wv into the three weight pairs
    ln_split_kernel<<<ROWS, 256>>>(x, g1, be1, Ahi, Alo);
    SPLIT(Wq, B1h, B1l, DW);
    SPLIT(Wk, B2h, B2l, DW);
    SPLIT(Wv, B3h, B3l, DW);

    // 2) merged QKV projection: 768 CTAs, rope fused for Q/K, fp32 v for V
    dim3 gQKV(2 * (3 * Dd / 256), ROWS / 256);   // (48, 16)
    mma_qkv_kernel<<<gQKV, GEMM_THREADS, GEMM_SMEM>>>(
        Ahi, Alo, B1h, B1l, B2h, B2l, B3h, B3l,
        bq, bk, bv, fr, fQh, fQl, fKh, fKl, v);

    // 3) V transpose+split
    vtrans_kernel<<<dim3(Tt / 64, HDd / 32, Bb * Hh), dim3(32, 8)>>>(v, fVh, fVl);

    // 4) causal flash attention (tcgen05), writing hi/lo directly
    flash_mma_kernel<<<dim3(Tt / 128, Hh, Bb), 256, FLASH_SMEM>>>(
        fQh, fQl, fKh, fKl, fVh, fVl, Ahi, Alo);

    // 5) output projection + residual(x) -> out
    dim3 gD(2 * (Dd / 256), ROWS / 256);
    SPLIT(Wo, B1h, B1l, DW);
    mma_gemm_kernel<<<gD, GEMM_THREADS, GEMM_SMEM>>>(
        Ahi, Alo, B1h, B1l, bo, x, out, nullptr, nullptr, nullptr, ROWS, Dd, Dd);

    // 6) LN2 -> Ahi/Alo
    ln_split_kernel<<<ROWS, 256>>>(out, g2, be2, Ahi, Alo);

    // 7) gate (fp32 ff1), then up with fused silu(gate)*u -> Shi/Slo
    dim3 gF(2 * (FFd / 256), ROWS / 256);
    SPLIT(Wg, B1h, B1l, FW);
    mma_gemm_kernel<<<gF, GEMM_THREADS, GEMM_SMEM>>>(
        Ahi, Alo, B1h, B1l, bg, nullptr, ff1, nullptr, nullptr, nullptr, ROWS, FFd, Dd);
    SPLIT(Wu, B2h, B2l, FW);
    mma_gemm_kernel<<<gF, GEMM_THREADS, GEMM_SMEM>>>(
        Ahi, Alo, B2h, B2l, bu, nullptr, nullptr, ff1, Shi, Slo, ROWS, FFd, Dd);

    // 9) down projection + residual(out) -> out
    SPLIT(Wd, B1h, B1l, FW);
    mma_gemm_kernel<<<gD, GEMM_THREADS, GEMM_SMEM>>>(
        Shi, Slo, B1h, B1l, bd, out, out, nullptr, nullptr, nullptr, ROWS, Dd, FFd);
}